// round 7
// baseline (speedup 1.0000x reference)
#include <cuda_runtime.h>
#include <cuda_bf16.h>
#include <cstdint>
#include <math.h>

#define Bb 2
#define Hh 16
#define Ss 2048
#define Dd 64
#define MT 128
#define KN 128
#define NTL (Ss/KN)
#define TPB 512
#define INV_TEMP 0.125f

// SMEM byte offsets
#define SM_QH 0
#define SM_QL 16384
#define SM_KH 32768
#define SM_KL 49152
#define SM_VH 65536
#define SM_VL 81920
#define SM_RAWK 98304
#define SM_RAWV 131072
#define SM_SENT 163840
#define SM_RINV 164352
#define SM_RS   164864
#define SMEM_BYTES 165888

__device__ __forceinline__ uint32_t smem_u32(const void* p) {
    uint32_t a; asm("{ .reg .u64 t; cvta.to.shared.u64 t, %1; cvt.u32.u64 %0, t; }" : "=r"(a) : "l"(p));
    return a;
}
__device__ __forceinline__ uint32_t sw128(uint32_t off) { return off ^ ((off >> 3) & 0x70); }

__device__ __forceinline__ void split2(float x0, float x1, uint32_t& hi, uint32_t& lo) {
    __nv_bfloat16 h0 = __float2bfloat16(x0), h1 = __float2bfloat16(x1);
    float r0 = x0 - __bfloat162float(h0), r1 = x1 - __bfloat162float(h1);
    __nv_bfloat162 H; H.x = h0; H.y = h1;
    __nv_bfloat162 L; L.x = __float2bfloat16(r0); L.y = __float2bfloat16(r1);
    hi = *(uint32_t*)&H; lo = *(uint32_t*)&L;
}

__device__ __forceinline__ void ldsm4(uint32_t* r, uint32_t addr) {
    asm volatile("ldmatrix.sync.aligned.m8n8.x4.shared.b16 {%0,%1,%2,%3}, [%4];"
        : "=r"(r[0]), "=r"(r[1]), "=r"(r[2]), "=r"(r[3]) : "r"(addr));
}
__device__ __forceinline__ void ldsm4t(uint32_t* r, uint32_t addr) {
    asm volatile("ldmatrix.sync.aligned.m8n8.x4.trans.shared.b16 {%0,%1,%2,%3}, [%4];"
        : "=r"(r[0]), "=r"(r[1]), "=r"(r[2]), "=r"(r[3]) : "r"(addr));
}
__device__ __forceinline__ void mma16816(float* c, const uint32_t* a, uint32_t b0, uint32_t b1) {
    asm volatile("mma.sync.aligned.m16n8k16.row.col.f32.bf16.bf16.f32 "
        "{%0,%1,%2,%3}, {%4,%5,%6,%7}, {%8,%9}, {%0,%1,%2,%3};"
        : "+f"(c[0]), "+f"(c[1]), "+f"(c[2]), "+f"(c[3])
        : "r"(a[0]), "r"(a[1]), "r"(a[2]), "r"(a[3]), "r"(b0), "r"(b1));
}
__device__ __forceinline__ void cp16(uint32_t saddr, const void* g) {
    asm volatile("cp.async.ca.shared.global [%0], [%1], 16;" :: "r"(saddr), "l"(g));
}
#define CP_COMMIT() asm volatile("cp.async.commit_group;" ::: "memory")
#define CP_WAIT0()  asm volatile("cp.async.wait_group 0;" ::: "memory")

__global__ void __launch_bounds__(TPB, 1)
attn_kernel(const float* __restrict__ Q, const float* __restrict__ K,
            const float* __restrict__ V, const float* __restrict__ SENT,
            const int* __restrict__ MASK,
            float* __restrict__ OUT, float* __restrict__ ATTN)
{
    extern __shared__ char sm[];
    const uint32_t sb = smem_u32(sm);
    const int tid = threadIdx.x, lane = tid & 31, wid = tid >> 5;
    const int wr = wid & 7;          // row group: rows wr*16..wr*16+15
    const int wc = wid >> 3;         // key half: keys wc*64..wc*64+63 of each tile
    const int q0 = blockIdx.x * MT;
    const int head = blockIdx.y;
    const int b = head >> 4;
    const size_t head_off = (size_t)head * Ss;

    float* sentm = (float*)(sm + SM_SENT);
    float* rinv  = (float*)(sm + SM_RINV);
    float* rs    = (float*)(sm + SM_RS);     // [2][128] partial rowsums

    // ---- stage Q -> bf16 hi/lo, swizzled (pre-scaled by 1/T) ----
    {
        const float4* qg = (const float4*)(Q + (head_off + q0) * Dd);
        #pragma unroll
        for (int u = 0; u < 2; u++) {
            int idx = u * TPB + tid;
            int r = idx >> 3, c = idx & 7;
            float4 a = qg[r * 16 + c * 2], bq = qg[r * 16 + c * 2 + 1];
            uint4 H, L;
            split2(a.x * INV_TEMP, a.y * INV_TEMP, H.x, L.x);
            split2(a.z * INV_TEMP, a.w * INV_TEMP, H.y, L.y);
            split2(bq.x * INV_TEMP, bq.y * INV_TEMP, H.z, L.z);
            split2(bq.z * INV_TEMP, bq.w * INV_TEMP, H.w, L.w);
            uint32_t off = sw128((uint32_t)(r * 128 + c * 16));
            *(uint4*)(sm + SM_QH + off) = H;
            *(uint4*)(sm + SM_QL + off) = L;
        }
    }
    // prefetch raw K tile 0
    {
        const char* kg = (const char*)(K + head_off * Dd);
        #pragma unroll
        for (int u = 0; u < 4; u++) {
            int i = u * TPB + tid;
            cp16(sb + SM_RAWK + i * 16, kg + i * 16);
        }
        CP_COMMIT();
    }
    __syncthreads();

    // ---- Q fragments (held all kernel) ----
    uint32_t qh[4][4], ql[4][4];
    {
        uint32_t rowq = (uint32_t)(wr * 16 + (lane & 15));
        #pragma unroll
        for (int kb = 0; kb < 4; kb++) {
            uint32_t off = sw128(rowq * 128 + ((uint32_t)(lane >> 4) + 2 * kb) * 16);
            ldsm4(qh[kb], sb + SM_QH + off);
            ldsm4(ql[kb], sb + SM_QL + off);
        }
    }
    CP_WAIT0();
    __syncthreads();

    const int row0 = wr * 16 + (lane >> 2);
    const int cb = 2 * (lane & 3);
    float rsum0 = 0.f, rsum1 = 0.f;

    // ================= Pass A: rowsums only =================
    for (int t = 0; t < NTL; t++) {
        const int j0 = t * KN;
        {   // convert K raw -> hi/lo
            const float4* rk = (const float4*)(sm + SM_RAWK);
            #pragma unroll
            for (int u = 0; u < 2; u++) {
                int idx = u * TPB + tid;
                int r = idx >> 3, c = idx & 7;
                uint32_t off = sw128((uint32_t)(r * 128 + c * 16));
                float4 a = rk[r * 16 + c * 2], bq = rk[r * 16 + c * 2 + 1];
                uint4 H, L;
                split2(a.x, a.y, H.x, L.x);  split2(a.z, a.w, H.y, L.y);
                split2(bq.x, bq.y, H.z, L.z); split2(bq.z, bq.w, H.w, L.w);
                *(uint4*)(sm + SM_KH + off) = H;
                *(uint4*)(sm + SM_KL + off) = L;
            }
            if (tid < KN)
                sentm[tid] = MASK[b * Ss + j0 + tid] ? SENT[b * Ss + j0 + tid] : 0.0f;
        }
        __syncthreads();
        if (t + 1 < NTL) {
            const char* kg = (const char*)(K + (head_off + j0 + KN) * Dd);
            #pragma unroll
            for (int u = 0; u < 4; u++) {
                int i = u * TPB + tid;
                cp16(sb + SM_RAWK + i * 16, kg + i * 16);
            }
            CP_COMMIT();
        }
        #pragma unroll
        for (int nb = 0; nb < 8; nb++) {
            const int nbg = wc * 8 + nb;
            float sacc[4] = {0.f, 0.f, 0.f, 0.f};
            uint32_t bh[8], bl[8];
            uint32_t rB = (uint32_t)(nbg * 8 + (lane & 7)) * 128;
            uint32_t ch = (uint32_t)(lane >> 3) * 16;
            ldsm4(bh,     sb + SM_KH + sw128(rB + ch));
            ldsm4(bh + 4, sb + SM_KH + sw128(rB + ch + 64));
            ldsm4(bl,     sb + SM_KL + sw128(rB + ch));
            ldsm4(bl + 4, sb + SM_KL + sw128(rB + ch + 64));
            #pragma unroll
            for (int kb = 0; kb < 4; kb++) {
                mma16816(sacc, qh[kb], bh[2 * kb], bh[2 * kb + 1]);
                mma16816(sacc, qh[kb], bl[2 * kb], bl[2 * kb + 1]);
                mma16816(sacc, ql[kb], bh[2 * kb], bh[2 * kb + 1]);
            }
            float2 s2 = *(float2*)&sentm[nbg * 8 + cb];
            rsum0 += __expf(sacc[0]) * s2.x + __expf(sacc[1]) * s2.y;
            rsum1 += __expf(sacc[2]) * s2.x + __expf(sacc[3]) * s2.y;
        }
        if (t + 1 < NTL) CP_WAIT0();
        __syncthreads();
    }

    // ---- reduce rowsums across quads and key halves ----
    rsum0 += __shfl_xor_sync(0xFFFFFFFFu, rsum0, 1);
    rsum0 += __shfl_xor_sync(0xFFFFFFFFu, rsum0, 2);
    rsum1 += __shfl_xor_sync(0xFFFFFFFFu, rsum1, 1);
    rsum1 += __shfl_xor_sync(0xFFFFFFFFu, rsum1, 2);
    if ((lane & 3) == 0) {
        rs[wc * 128 + row0]     = rsum0;
        rs[wc * 128 + row0 + 8] = rsum1;
    }
    __syncthreads();
    if (tid < MT) rinv[tid] = 1.0f / (rs[tid] + rs[128 + tid]);
    // prefetch raw K,V tile 0 for pass B
    {
        const char* kg = (const char*)(K + head_off * Dd);
        const char* vg = (const char*)(V + head_off * Dd);
        #pragma unroll
        for (int u = 0; u < 4; u++) {
            int i = u * TPB + tid;
            cp16(sb + SM_RAWK + i * 16, kg + i * 16);
            cp16(sb + SM_RAWV + i * 16, vg + i * 16);
        }
        CP_COMMIT();
        CP_WAIT0();
    }
    __syncthreads();

    const float inv0 = rinv[row0], inv1 = rinv[row0 + 8];
    float* arow0 = ATTN + (head_off + q0 + row0) * (size_t)Ss;
    float* arow1 = arow0 + 8 * (size_t)Ss;

    float oacc[8][4];
    #pragma unroll
    for (int nb = 0; nb < 8; nb++)
        #pragma unroll
        for (int i = 0; i < 4; i++) oacc[nb][i] = 0.f;

    // ================= Pass B: normalized attn + PV =================
    for (int t = 0; t < NTL; t++) {
        const int j0 = t * KN;
        {   // convert K and V raw -> hi/lo
            const float4* rk = (const float4*)(sm + SM_RAWK);
            const float4* rv = (const float4*)(sm + SM_RAWV);
            #pragma unroll
            for (int u = 0; u < 2; u++) {
                int idx = u * TPB + tid;
                int r = idx >> 3, c = idx & 7;
                uint32_t off = sw128((uint32_t)(r * 128 + c * 16));
                float4 a = rk[r * 16 + c * 2], bq = rk[r * 16 + c * 2 + 1];
                uint4 H, L;
                split2(a.x, a.y, H.x, L.x);  split2(a.z, a.w, H.y, L.y);
                split2(bq.x, bq.y, H.z, L.z); split2(bq.z, bq.w, H.w, L.w);
                *(uint4*)(sm + SM_KH + off) = H;
                *(uint4*)(sm + SM_KL + off) = L;
                a = rv[r * 16 + c * 2]; bq = rv[r * 16 + c * 2 + 1];
                split2(a.x, a.y, H.x, L.x);  split2(a.z, a.w, H.y, L.y);
                split2(bq.x, bq.y, H.z, L.z); split2(bq.z, bq.w, H.w, L.w);
                *(uint4*)(sm + SM_VH + off) = H;
                *(uint4*)(sm + SM_VL + off) = L;
            }
            if (tid < KN)
                sentm[tid] = MASK[b * Ss + j0 + tid] ? SENT[b * Ss + j0 + tid] : 0.0f;
        }
        __syncthreads();
        if (t + 1 < NTL) {
            const char* kg = (const char*)(K + (head_off + j0 + KN) * Dd);
            const char* vg = (const char*)(V + (head_off + j0 + KN) * Dd);
            #pragma unroll
            for (int u = 0; u < 4; u++) {
                int i = u * TPB + tid;
                cp16(sb + SM_RAWK + i * 16, kg + i * 16);
                cp16(sb + SM_RAWV + i * 16, vg + i * 16);
            }
            CP_COMMIT();
        }

        // ---- QK + epilogue (normalized p) ----
        uint32_t pah[4][4], pal[4][4];
        #pragma unroll
        for (int nb = 0; nb < 8; nb++) {
            const int nbg = wc * 8 + nb;
            float sacc[4] = {0.f, 0.f, 0.f, 0.f};
            uint32_t bh[8], bl[8];
            uint32_t rB = (uint32_t)(nbg * 8 + (lane & 7)) * 128;
            uint32_t ch = (uint32_t)(lane >> 3) * 16;
            ldsm4(bh,     sb + SM_KH + sw128(rB + ch));
            ldsm4(bh + 4, sb + SM_KH + sw128(rB + ch + 64));
            ldsm4(bl,     sb + SM_KL + sw128(rB + ch));
            ldsm4(bl + 4, sb + SM_KL + sw128(rB + ch + 64));
            #pragma unroll
            for (int kb = 0; kb < 4; kb++) {
                mma16816(sacc, qh[kb], bh[2 * kb], bh[2 * kb + 1]);
                mma16816(sacc, qh[kb], bl[2 * kb], bl[2 * kb + 1]);
                mma16816(sacc, ql[kb], bh[2 * kb], bh[2 * kb + 1]);
            }
            float2 s2 = *(float2*)&sentm[nbg * 8 + cb];
            float p0 = __expf(sacc[0]) * s2.x * inv0;
            float p1 = __expf(sacc[1]) * s2.y * inv0;
            float p2 = __expf(sacc[2]) * s2.x * inv1;
            float p3 = __expf(sacc[3]) * s2.y * inv1;
            *(float2*)(arow0 + j0 + nbg * 8 + cb) = make_float2(p0, p1);
            *(float2*)(arow1 + j0 + nbg * 8 + cb) = make_float2(p2, p3);
            const int kb = nb >> 1, hf = (nb & 1) * 2;
            split2(p0, p1, pah[kb][hf],     pal[kb][hf]);
            split2(p2, p3, pah[kb][hf + 1], pal[kb][hf + 1]);
        }

        // ---- PV over this warp's 64 keys ----
        #pragma unroll
        for (int kb = 0; kb < 4; kb++) {
            const int kbg = wc * 4 + kb;
            uint32_t vh[16], vl[16];
            uint32_t rV = (uint32_t)(kbg * 16 + (lane & 15)) * 128;
            uint32_t chv = (uint32_t)(lane >> 4) * 16;
            #pragma unroll
            for (int qd = 0; qd < 4; qd++) {
                ldsm4t(vh + 4 * qd, sb + SM_VH + sw128(rV + chv + qd * 32));
                ldsm4t(vl + 4 * qd, sb + SM_VL + sw128(rV + chv + qd * 32));
            }
            #pragma unroll
            for (int nb = 0; nb < 8; nb++) {
                mma16816(oacc[nb], pah[kb], vh[2 * nb], vh[2 * nb + 1]);
                mma16816(oacc[nb], pal[kb], vh[2 * nb], vh[2 * nb + 1]);
                mma16816(oacc[nb], pah[kb], vl[2 * nb], vl[2 * nb + 1]);
            }
        }

        if (t + 1 < NTL) CP_WAIT0();
        __syncthreads();
    }

    // ---- reduce oacc across key halves, write OUT (already normalized) ----
    float* buf = (float*)(sm + SM_RAWK);
    if (wc == 1) {
        const int base = (wr * 32 + lane) * 32;
        #pragma unroll
        for (int nb = 0; nb < 8; nb++)
            #pragma unroll
            for (int i = 0; i < 4; i++) buf[base + nb * 4 + i] = oacc[nb][i];
    }
    __syncthreads();
    if (wc == 0) {
        const int base = (wr * 32 + lane) * 32;
        float2* o0 = (float2*)(OUT + (head_off + q0 + row0) * (size_t)Dd);
        float2* o1 = (float2*)(OUT + (head_off + q0 + row0 + 8) * (size_t)Dd);
        #pragma unroll
        for (int nb = 0; nb < 8; nb++) {
            float a0 = oacc[nb][0] + buf[base + nb * 4 + 0];
            float a1 = oacc[nb][1] + buf[base + nb * 4 + 1];
            float a2 = oacc[nb][2] + buf[base + nb * 4 + 2];
            float a3 = oacc[nb][3] + buf[base + nb * 4 + 3];
            o0[nb * 4 + (lane & 3)] = make_float2(a0, a1);
            o1[nb * 4 + (lane & 3)] = make_float2(a2, a3);
        }
    }
}

extern "C" void kernel_launch(void* const* d_in, const int* in_sizes, int n_in,
                              void* d_out, int out_size)
{
    const float* q    = (const float*)d_in[0];
    const float* k    = (const float*)d_in[1];
    const float* v    = (const float*)d_in[2];
    const float* sent = (const float*)d_in[3];
    const int*   mask = (const int*)d_in[4];

    float* out  = (float*)d_out;                    // [B,H,S,D]
    float* attn = out + (size_t)Bb * Hh * Ss * Dd;  // [B,H,S,S]

    cudaFuncSetAttribute(attn_kernel, cudaFuncAttributeMaxDynamicSharedMemorySize, SMEM_BYTES);

    dim3 grid(Ss / MT, Bb * Hh);
    attn_kernel<<<grid, TPB, SMEM_BYTES>>>(q, k, v, sent, mask, out, attn);
}

// round 8
// speedup vs baseline: 1.4597x; 1.4597x over previous
#include <cuda_runtime.h>
#include <cuda_bf16.h>
#include <cstdint>
#include <math.h>

#define Bb 2
#define Hh 16
#define Ss 2048
#define Dd 64
#define MT 128
#define KN 128
#define NTL (Ss/KN)
#define TPB 256
#define INV_TEMP 0.125f

// SMEM byte offsets
#define SM_QH 0
#define SM_QL 16384
#define SM_KH 32768
#define SM_KL 49152
#define SM_VH 65536
#define SM_VL 81920
#define SM_RAWK 98304
#define SM_RAWV 131072
#define SM_SENT 163840
#define SMEM_BYTES 164352

__device__ __forceinline__ uint32_t smem_u32(const void* p) {
    uint32_t a; asm("{ .reg .u64 t; cvta.to.shared.u64 t, %1; cvt.u32.u64 %0, t; }" : "=r"(a) : "l"(p));
    return a;
}
__device__ __forceinline__ uint32_t sw128(uint32_t off) { return off ^ ((off >> 3) & 0x70); }

__device__ __forceinline__ void split2(float x0, float x1, uint32_t& hi, uint32_t& lo) {
    __nv_bfloat16 h0 = __float2bfloat16(x0), h1 = __float2bfloat16(x1);
    float r0 = x0 - __bfloat162float(h0), r1 = x1 - __bfloat162float(h1);
    __nv_bfloat162 H; H.x = h0; H.y = h1;
    __nv_bfloat162 L; L.x = __float2bfloat16(r0); L.y = __float2bfloat16(r1);
    hi = *(uint32_t*)&H; lo = *(uint32_t*)&L;
}

__device__ __forceinline__ void ldsm4(uint32_t* r, uint32_t addr) {
    asm volatile("ldmatrix.sync.aligned.m8n8.x4.shared.b16 {%0,%1,%2,%3}, [%4];"
        : "=r"(r[0]), "=r"(r[1]), "=r"(r[2]), "=r"(r[3]) : "r"(addr));
}
__device__ __forceinline__ void ldsm4t(uint32_t* r, uint32_t addr) {
    asm volatile("ldmatrix.sync.aligned.m8n8.x4.trans.shared.b16 {%0,%1,%2,%3}, [%4];"
        : "=r"(r[0]), "=r"(r[1]), "=r"(r[2]), "=r"(r[3]) : "r"(addr));
}
__device__ __forceinline__ void mma16816(float* c, const uint32_t* a, uint32_t b0, uint32_t b1) {
    asm volatile("mma.sync.aligned.m16n8k16.row.col.f32.bf16.bf16.f32 "
        "{%0,%1,%2,%3}, {%4,%5,%6,%7}, {%8,%9}, {%0,%1,%2,%3};"
        : "+f"(c[0]), "+f"(c[1]), "+f"(c[2]), "+f"(c[3])
        : "r"(a[0]), "r"(a[1]), "r"(a[2]), "r"(a[3]), "r"(b0), "r"(b1));
}
__device__ __forceinline__ void cp16(uint32_t saddr, const void* g) {
    asm volatile("cp.async.ca.shared.global [%0], [%1], 16;" :: "r"(saddr), "l"(g));
}
#define CP_COMMIT() asm volatile("cp.async.commit_group;" ::: "memory")
#define CP_WAIT0()  asm volatile("cp.async.wait_group 0;" ::: "memory")

__global__ void __launch_bounds__(TPB, 1)
attn_kernel(const float* __restrict__ Q, const float* __restrict__ K,
            const float* __restrict__ V, const float* __restrict__ SENT,
            const int* __restrict__ MASK,
            float* __restrict__ OUT, float* __restrict__ ATTN)
{
    extern __shared__ char sm[];
    const uint32_t sb = smem_u32(sm);
    const int tid = threadIdx.x, lane = tid & 31, wid = tid >> 5;
    const int q0 = blockIdx.x * MT;
    const int head = blockIdx.y;
    const int b = head >> 4;
    const size_t head_off = (size_t)head * Ss;

    float* sentm = (float*)(sm + SM_SENT);

    // ---- stage Q -> bf16 hi/lo, swizzled (pre-scaled by 1/T) ----
    {
        const float4* qg = (const float4*)(Q + (head_off + q0) * Dd);
        #pragma unroll
        for (int u = 0; u < 4; u++) {
            int idx = u * TPB + tid;
            int r = idx >> 3, c = idx & 7;
            float4 a = qg[r * 16 + c * 2], bq = qg[r * 16 + c * 2 + 1];
            uint4 H, L;
            split2(a.x * INV_TEMP, a.y * INV_TEMP, H.x, L.x);
            split2(a.z * INV_TEMP, a.w * INV_TEMP, H.y, L.y);
            split2(bq.x * INV_TEMP, bq.y * INV_TEMP, H.z, L.z);
            split2(bq.z * INV_TEMP, bq.w * INV_TEMP, H.w, L.w);
            uint32_t off = sw128((uint32_t)(r * 128 + c * 16));
            *(uint4*)(sm + SM_QH + off) = H;
            *(uint4*)(sm + SM_QL + off) = L;
        }
    }
    // prefetch raw K tile 0 (pass A needs K only)
    {
        const char* kg = (const char*)(K + head_off * Dd);
        #pragma unroll
        for (int u = 0; u < 8; u++) {
            int i = u * TPB + tid;
            cp16(sb + SM_RAWK + i * 16, kg + i * 16);
        }
        CP_COMMIT();
    }
    __syncthreads();

    // ---- Q fragments (held all kernel) ----
    uint32_t qh[4][4], ql[4][4];
    {
        uint32_t rowq = (uint32_t)(wid * 16 + (lane & 15));
        #pragma unroll
        for (int kb = 0; kb < 4; kb++) {
            uint32_t off = sw128(rowq * 128 + ((uint32_t)(lane >> 4) + 2 * kb) * 16);
            ldsm4(qh[kb], sb + SM_QH + off);
            ldsm4(ql[kb], sb + SM_QL + off);
        }
    }
    CP_WAIT0();
    __syncthreads();

    const int row0 = wid * 16 + (lane >> 2);
    const int cb = 2 * (lane & 3);
    float rsum0 = 0.f, rsum1 = 0.f;

    // ================= Pass A: rowsums only (K only) =================
    for (int t = 0; t < NTL; t++) {
        const int j0 = t * KN;
        {   // convert K raw -> hi/lo
            const float4* rk = (const float4*)(sm + SM_RAWK);
            #pragma unroll
            for (int u = 0; u < 4; u++) {
                int idx = u * TPB + tid;
                int r = idx >> 3, c = idx & 7;
                uint32_t off = sw128((uint32_t)(r * 128 + c * 16));
                float4 a = rk[r * 16 + c * 2], bq = rk[r * 16 + c * 2 + 1];
                uint4 H, L;
                split2(a.x, a.y, H.x, L.x);  split2(a.z, a.w, H.y, L.y);
                split2(bq.x, bq.y, H.z, L.z); split2(bq.z, bq.w, H.w, L.w);
                *(uint4*)(sm + SM_KH + off) = H;
                *(uint4*)(sm + SM_KL + off) = L;
            }
            if (tid < KN)
                sentm[tid] = MASK[b * Ss + j0 + tid] ? SENT[b * Ss + j0 + tid] : 0.0f;
        }
        __syncthreads();
        if (t + 1 < NTL) {
            const char* kg = (const char*)(K + (head_off + j0 + KN) * Dd);
            #pragma unroll
            for (int u = 0; u < 8; u++) {
                int i = u * TPB + tid;
                cp16(sb + SM_RAWK + i * 16, kg + i * 16);
            }
            CP_COMMIT();
        }
        #pragma unroll
        for (int nb = 0; nb < 16; nb++) {
            float sacc[4] = {0.f, 0.f, 0.f, 0.f};
            uint32_t bh[8], bl[8];
            uint32_t rB = (uint32_t)(nb * 8 + (lane & 7)) * 128;
            uint32_t ch = (uint32_t)(lane >> 3) * 16;
            ldsm4(bh,     sb + SM_KH + sw128(rB + ch));
            ldsm4(bh + 4, sb + SM_KH + sw128(rB + ch + 64));
            ldsm4(bl,     sb + SM_KL + sw128(rB + ch));
            ldsm4(bl + 4, sb + SM_KL + sw128(rB + ch + 64));
            #pragma unroll
            for (int kb = 0; kb < 4; kb++) {
                mma16816(sacc, qh[kb], bh[2 * kb], bh[2 * kb + 1]);
                mma16816(sacc, qh[kb], bl[2 * kb], bl[2 * kb + 1]);
                mma16816(sacc, ql[kb], bh[2 * kb], bh[2 * kb + 1]);
            }
            float2 s2 = *(float2*)&sentm[nb * 8 + cb];
            rsum0 += __expf(sacc[0]) * s2.x + __expf(sacc[1]) * s2.y;
            rsum1 += __expf(sacc[2]) * s2.x + __expf(sacc[3]) * s2.y;
        }
        if (t + 1 < NTL) CP_WAIT0();
        __syncthreads();
    }

    // ---- rowsum reduce within quads (warp owns full key range of its rows) ----
    rsum0 += __shfl_xor_sync(0xFFFFFFFFu, rsum0, 1);
    rsum0 += __shfl_xor_sync(0xFFFFFFFFu, rsum0, 2);
    rsum1 += __shfl_xor_sync(0xFFFFFFFFu, rsum1, 1);
    rsum1 += __shfl_xor_sync(0xFFFFFFFFu, rsum1, 2);
    const float inv0 = 1.0f / rsum0, inv1 = 1.0f / rsum1;

    // prefetch raw K,V tile 0 for pass B
    {
        const char* kg = (const char*)(K + head_off * Dd);
        const char* vg = (const char*)(V + head_off * Dd);
        #pragma unroll
        for (int u = 0; u < 8; u++) {
            int i = u * TPB + tid;
            cp16(sb + SM_RAWK + i * 16, kg + i * 16);
            cp16(sb + SM_RAWV + i * 16, vg + i * 16);
        }
        CP_COMMIT();
        CP_WAIT0();
    }
    __syncthreads();

    float oacc[8][4];
    #pragma unroll
    for (int nb = 0; nb < 8; nb++)
        #pragma unroll
        for (int i = 0; i < 4; i++) oacc[nb][i] = 0.f;

    float* arow0 = ATTN + (head_off + q0 + row0) * (size_t)Ss;
    float* arow1 = arow0 + 8 * (size_t)Ss;

    // ================= Pass B: normalized attn write + PV =================
    for (int t = 0; t < NTL; t++) {
        const int j0 = t * KN;
        {   // convert K and V raw -> hi/lo
            const float4* rk = (const float4*)(sm + SM_RAWK);
            const float4* rv = (const float4*)(sm + SM_RAWV);
            #pragma unroll
            for (int u = 0; u < 4; u++) {
                int idx = u * TPB + tid;
                int r = idx >> 3, c = idx & 7;
                uint32_t off = sw128((uint32_t)(r * 128 + c * 16));
                float4 a = rk[r * 16 + c * 2], bq = rk[r * 16 + c * 2 + 1];
                uint4 H, L;
                split2(a.x, a.y, H.x, L.x);  split2(a.z, a.w, H.y, L.y);
                split2(bq.x, bq.y, H.z, L.z); split2(bq.z, bq.w, H.w, L.w);
                *(uint4*)(sm + SM_KH + off) = H;
                *(uint4*)(sm + SM_KL + off) = L;
                a = rv[r * 16 + c * 2]; bq = rv[r * 16 + c * 2 + 1];
                split2(a.x, a.y, H.x, L.x);  split2(a.z, a.w, H.y, L.y);
                split2(bq.x, bq.y, H.z, L.z); split2(bq.z, bq.w, H.w, L.w);
                *(uint4*)(sm + SM_VH + off) = H;
                *(uint4*)(sm + SM_VL + off) = L;
            }
            if (tid < KN)
                sentm[tid] = MASK[b * Ss + j0 + tid] ? SENT[b * Ss + j0 + tid] : 0.0f;
        }
        __syncthreads();

        if (t + 1 < NTL) {
            const char* kg = (const char*)(K + (head_off + j0 + KN) * Dd);
            const char* vg = (const char*)(V + (head_off + j0 + KN) * Dd);
            #pragma unroll
            for (int u = 0; u < 8; u++) {
                int i = u * TPB + tid;
                cp16(sb + SM_RAWK + i * 16, kg + i * 16);
                cp16(sb + SM_RAWV + i * 16, vg + i * 16);
            }
            CP_COMMIT();
        }

        // ---- QK + epilogue: p = exp(s)*sent*mask*inv (normalized) ----
        uint32_t pah[8][4], pal[8][4];
        #pragma unroll
        for (int nb = 0; nb < 16; nb++) {
            float sacc[4] = {0.f, 0.f, 0.f, 0.f};
            uint32_t bh[8], bl[8];
            uint32_t rB = (uint32_t)(nb * 8 + (lane & 7)) * 128;
            uint32_t ch = (uint32_t)(lane >> 3) * 16;
            ldsm4(bh,     sb + SM_KH + sw128(rB + ch));
            ldsm4(bh + 4, sb + SM_KH + sw128(rB + ch + 64));
            ldsm4(bl,     sb + SM_KL + sw128(rB + ch));
            ldsm4(bl + 4, sb + SM_KL + sw128(rB + ch + 64));
            #pragma unroll
            for (int kb = 0; kb < 4; kb++) {
                mma16816(sacc, qh[kb], bh[2 * kb], bh[2 * kb + 1]);
                mma16816(sacc, qh[kb], bl[2 * kb], bl[2 * kb + 1]);
                mma16816(sacc, ql[kb], bh[2 * kb], bh[2 * kb + 1]);
            }
            float2 s2 = *(float2*)&sentm[nb * 8 + cb];
            float p0 = __expf(sacc[0]) * s2.x * inv0;
            float p1 = __expf(sacc[1]) * s2.y * inv0;
            float p2 = __expf(sacc[2]) * s2.x * inv1;
            float p3 = __expf(sacc[3]) * s2.y * inv1;
            *(float2*)(arow0 + j0 + nb * 8 + cb) = make_float2(p0, p1);
            *(float2*)(arow1 + j0 + nb * 8 + cb) = make_float2(p2, p3);
            const int kb = nb >> 1, hf = (nb & 1) * 2;
            split2(p0, p1, pah[kb][hf],     pal[kb][hf]);
            split2(p2, p3, pah[kb][hf + 1], pal[kb][hf + 1]);
        }

        // ---- PV ----
        #pragma unroll
        for (int kb = 0; kb < 8; kb++) {
            uint32_t vh[16], vl[16];
            uint32_t rV = (uint32_t)(kb * 16 + (lane & 15)) * 128;
            uint32_t chv = (uint32_t)(lane >> 4) * 16;
            #pragma unroll
            for (int qd = 0; qd < 4; qd++) {
                ldsm4t(vh + 4 * qd, sb + SM_VH + sw128(rV + chv + qd * 32));
                ldsm4t(vl + 4 * qd, sb + SM_VL + sw128(rV + chv + qd * 32));
            }
            #pragma unroll
            for (int nb = 0; nb < 8; nb++) {
                mma16816(oacc[nb], pah[kb], vh[2 * nb], vh[2 * nb + 1]);
                mma16816(oacc[nb], pal[kb], vh[2 * nb], vh[2 * nb + 1]);
                mma16816(oacc[nb], pah[kb], vl[2 * nb], vl[2 * nb + 1]);
            }
        }

        if (t + 1 < NTL) CP_WAIT0();
        __syncthreads();
    }

    // ---- write out (already normalized) ----
    {
        float2* o0 = (float2*)(OUT + (head_off + q0 + row0) * (size_t)Dd);
        float2* o1 = (float2*)(OUT + (head_off + q0 + row0 + 8) * (size_t)Dd);
        #pragma unroll
        for (int nb = 0; nb < 8; nb++) {
            o0[nb * 4 + (lane & 3)] = make_float2(oacc[nb][0], oacc[nb][1]);
            o1[nb * 4 + (lane & 3)] = make_float2(oacc[nb][2], oacc[nb][3]);
        }
    }
}

extern "C" void kernel_launch(void* const* d_in, const int* in_sizes, int n_in,
                              void* d_out, int out_size)
{
    const float* q    = (const float*)d_in[0];
    const float* k    = (const float*)d_in[1];
    const float* v    = (const float*)d_in[2];
    const float* sent = (const float*)d_in[3];
    const int*   mask = (const int*)d_in[4];

    float* out  = (float*)d_out;                    // [B,H,S,D]
    float* attn = out + (size_t)Bb * Hh * Ss * Dd;  // [B,H,S,S]

    cudaFuncSetAttribute(attn_kernel, cudaFuncAttributeMaxDynamicSharedMemorySize, SMEM_BYTES);

    dim3 grid(Ss / MT, Bb * Hh);
    attn_kernel<<<grid, TPB, SMEM_BYTES>>>(q, k, v, sent, mask, out, attn);
}

// round 9
// speedup vs baseline: 2.0302x; 1.3909x over previous
#include <cuda_runtime.h>
#include <cuda_fp16.h>
#include <cstdint>
#include <math.h>

#define Bb 2
#define Hh 16
#define Ss 2048
#define Dd 64
#define MT 128
#define KN 128
#define NTL (Ss/KN)
#define TPB 256
#define INV_TEMP 0.125f

// SMEM byte offsets
#define SM_QH 0
#define SM_KH 16384
#define SM_KL 32768
#define SM_VH 49152
#define SM_VL 65536
#define SM_RAWK 81920
#define SM_RAWV 114688
#define SM_SENT 147456
#define SMEM_BYTES 147968

__device__ __forceinline__ uint32_t smem_u32(const void* p) {
    uint32_t a; asm("{ .reg .u64 t; cvta.to.shared.u64 t, %1; cvt.u32.u64 %0, t; }" : "=r"(a) : "l"(p));
    return a;
}
__device__ __forceinline__ uint32_t sw128(uint32_t off) { return off ^ ((off >> 3) & 0x70); }

__device__ __forceinline__ uint32_t cvt2h(float x0, float x1) {
    __half2 H = __floats2half2_rn(x0, x1);
    return *(uint32_t*)&H;
}
__device__ __forceinline__ void split2h(float x0, float x1, uint32_t& hi, uint32_t& lo) {
    __half2 H = __floats2half2_rn(x0, x1);
    float r0 = x0 - __low2float(H), r1 = x1 - __high2float(H);
    __half2 L = __floats2half2_rn(r0, r1);
    hi = *(uint32_t*)&H; lo = *(uint32_t*)&L;
}

__device__ __forceinline__ void ldsm4(uint32_t* r, uint32_t addr) {
    asm volatile("ldmatrix.sync.aligned.m8n8.x4.shared.b16 {%0,%1,%2,%3}, [%4];"
        : "=r"(r[0]), "=r"(r[1]), "=r"(r[2]), "=r"(r[3]) : "r"(addr));
}
__device__ __forceinline__ void ldsm4t(uint32_t* r, uint32_t addr) {
    asm volatile("ldmatrix.sync.aligned.m8n8.x4.trans.shared.b16 {%0,%1,%2,%3}, [%4];"
        : "=r"(r[0]), "=r"(r[1]), "=r"(r[2]), "=r"(r[3]) : "r"(addr));
}
// NOTE: non-volatile — register deps carry correctness, lets ptxas interleave chains
__device__ __forceinline__ void mma16816(float* c, const uint32_t* a, uint32_t b0, uint32_t b1) {
    asm("mma.sync.aligned.m16n8k16.row.col.f32.f16.f16.f32 "
        "{%0,%1,%2,%3}, {%4,%5,%6,%7}, {%8,%9}, {%0,%1,%2,%3};"
        : "+f"(c[0]), "+f"(c[1]), "+f"(c[2]), "+f"(c[3])
        : "r"(a[0]), "r"(a[1]), "r"(a[2]), "r"(a[3]), "r"(b0), "r"(b1));
}
__device__ __forceinline__ void cp16(uint32_t saddr, const void* g) {
    asm volatile("cp.async.ca.shared.global [%0], [%1], 16;" :: "r"(saddr), "l"(g));
}
#define CP_COMMIT() asm volatile("cp.async.commit_group;" ::: "memory")
#define CP_WAIT0()  asm volatile("cp.async.wait_group 0;" ::: "memory")

__global__ void __launch_bounds__(TPB, 1)
attn_kernel(const float* __restrict__ Q, const float* __restrict__ K,
            const float* __restrict__ V, const float* __restrict__ SENT,
            const int* __restrict__ MASK,
            float* __restrict__ OUT, float* __restrict__ ATTN)
{
    extern __shared__ char sm[];
    const uint32_t sb = smem_u32(sm);
    const int tid = threadIdx.x, lane = tid & 31, wid = tid >> 5;
    const int q0 = blockIdx.x * MT;
    const int head = blockIdx.y;
    const int b = head >> 4;
    const size_t head_off = (size_t)head * Ss;

    float* sentm = (float*)(sm + SM_SENT);

    // ---- stage Q -> fp16 (single term, pre-scaled by 1/T), swizzled ----
    {
        const float4* qg = (const float4*)(Q + (head_off + q0) * Dd);
        #pragma unroll
        for (int u = 0; u < 4; u++) {
            int idx = u * TPB + tid;
            int r = idx >> 3, c = idx & 7;
            float4 a = qg[r * 16 + c * 2], bq = qg[r * 16 + c * 2 + 1];
            uint4 H;
            H.x = cvt2h(a.x * INV_TEMP, a.y * INV_TEMP);
            H.y = cvt2h(a.z * INV_TEMP, a.w * INV_TEMP);
            H.z = cvt2h(bq.x * INV_TEMP, bq.y * INV_TEMP);
            H.w = cvt2h(bq.z * INV_TEMP, bq.w * INV_TEMP);
            *(uint4*)(sm + SM_QH + sw128((uint32_t)(r * 128 + c * 16))) = H;
        }
    }
    // prefetch raw K tile 0
    {
        const char* kg = (const char*)(K + head_off * Dd);
        #pragma unroll
        for (int u = 0; u < 8; u++) {
            int i = u * TPB + tid;
            cp16(sb + SM_RAWK + i * 16, kg + i * 16);
        }
        CP_COMMIT();
    }
    __syncthreads();

    // ---- Q fragments (held all kernel) ----
    uint32_t qh[4][4];
    {
        uint32_t rowq = (uint32_t)(wid * 16 + (lane & 15));
        #pragma unroll
        for (int kb = 0; kb < 4; kb++)
            ldsm4(qh[kb], sb + SM_QH + sw128(rowq * 128 + ((uint32_t)(lane >> 4) + 2 * kb) * 16));
    }
    CP_WAIT0();
    __syncthreads();

    const int row0 = wid * 16 + (lane >> 2);
    const int cb = 2 * (lane & 3);
    float rsum0 = 0.f, rsum1 = 0.f;

    // ================= Pass A: rowsums only (qh·kh) =================
    for (int t = 0; t < NTL; t++) {
        const int j0 = t * KN;
        {   // convert K raw -> kh only
            const float4* rk = (const float4*)(sm + SM_RAWK);
            #pragma unroll
            for (int u = 0; u < 4; u++) {
                int idx = u * TPB + tid;
                int r = idx >> 3, c = idx & 7;
                float4 a = rk[r * 16 + c * 2], bq = rk[r * 16 + c * 2 + 1];
                uint4 H;
                H.x = cvt2h(a.x, a.y);  H.y = cvt2h(a.z, a.w);
                H.z = cvt2h(bq.x, bq.y); H.w = cvt2h(bq.z, bq.w);
                *(uint4*)(sm + SM_KH + sw128((uint32_t)(r * 128 + c * 16))) = H;
            }
            if (tid < KN)
                sentm[tid] = MASK[b * Ss + j0 + tid] ? SENT[b * Ss + j0 + tid] : 0.0f;
        }
        __syncthreads();
        if (t + 1 < NTL) {
            const char* kg = (const char*)(K + (head_off + j0 + KN) * Dd);
            #pragma unroll
            for (int u = 0; u < 8; u++) {
                int i = u * TPB + tid;
                cp16(sb + SM_RAWK + i * 16, kg + i * 16);
            }
            CP_COMMIT();
        }
        #pragma unroll
        for (int nb = 0; nb < 16; nb++) {
            float sacc[4] = {0.f, 0.f, 0.f, 0.f};
            uint32_t bh[8];
            uint32_t rB = (uint32_t)(nb * 8 + (lane & 7)) * 128;
            uint32_t ch = (uint32_t)(lane >> 3) * 16;
            ldsm4(bh,     sb + SM_KH + sw128(rB + ch));
            ldsm4(bh + 4, sb + SM_KH + sw128(rB + ch + 64));
            #pragma unroll
            for (int kb = 0; kb < 4; kb++)
                mma16816(sacc, qh[kb], bh[2 * kb], bh[2 * kb + 1]);
            float2 s2 = *(float2*)&sentm[nb * 8 + cb];
            rsum0 += __expf(sacc[0]) * s2.x + __expf(sacc[1]) * s2.y;
            rsum1 += __expf(sacc[2]) * s2.x + __expf(sacc[3]) * s2.y;
        }
        if (t + 1 < NTL) CP_WAIT0();
        __syncthreads();
    }

    // ---- rowsum reduce within quads ----
    rsum0 += __shfl_xor_sync(0xFFFFFFFFu, rsum0, 1);
    rsum0 += __shfl_xor_sync(0xFFFFFFFFu, rsum0, 2);
    rsum1 += __shfl_xor_sync(0xFFFFFFFFu, rsum1, 1);
    rsum1 += __shfl_xor_sync(0xFFFFFFFFu, rsum1, 2);
    const float inv0 = 1.0f / rsum0, inv1 = 1.0f / rsum1;

    // prefetch raw K,V tile 0 for pass B
    {
        const char* kg = (const char*)(K + head_off * Dd);
        const char* vg = (const char*)(V + head_off * Dd);
        #pragma unroll
        for (int u = 0; u < 8; u++) {
            int i = u * TPB + tid;
            cp16(sb + SM_RAWK + i * 16, kg + i * 16);
            cp16(sb + SM_RAWV + i * 16, vg + i * 16);
        }
        CP_COMMIT();
        CP_WAIT0();
    }
    __syncthreads();

    float oacc[8][4];
    #pragma unroll
    for (int nb = 0; nb < 8; nb++)
        #pragma unroll
        for (int i = 0; i < 4; i++) oacc[nb][i] = 0.f;

    float* arow0 = ATTN + (head_off + q0 + row0) * (size_t)Ss;
    float* arow1 = arow0 + 8 * (size_t)Ss;

    // ================= Pass B: normalized attn write + PV =================
    for (int t = 0; t < NTL; t++) {
        const int j0 = t * KN;
        {   // convert K (hi/lo) and V (hi/lo)
            const float4* rk = (const float4*)(sm + SM_RAWK);
            const float4* rv = (const float4*)(sm + SM_RAWV);
            #pragma unroll
            for (int u = 0; u < 4; u++) {
                int idx = u * TPB + tid;
                int r = idx >> 3, c = idx & 7;
                uint32_t off = sw128((uint32_t)(r * 128 + c * 16));
                float4 a = rk[r * 16 + c * 2], bq = rk[r * 16 + c * 2 + 1];
                uint4 H, L;
                split2h(a.x, a.y, H.x, L.x);  split2h(a.z, a.w, H.y, L.y);
                split2h(bq.x, bq.y, H.z, L.z); split2h(bq.z, bq.w, H.w, L.w);
                *(uint4*)(sm + SM_KH + off) = H;
                *(uint4*)(sm + SM_KL + off) = L;
                a = rv[r * 16 + c * 2]; bq = rv[r * 16 + c * 2 + 1];
                split2h(a.x, a.y, H.x, L.x);  split2h(a.z, a.w, H.y, L.y);
                split2h(bq.x, bq.y, H.z, L.z); split2h(bq.z, bq.w, H.w, L.w);
                *(uint4*)(sm + SM_VH + off) = H;
                *(uint4*)(sm + SM_VL + off) = L;
            }
            if (tid < KN)
                sentm[tid] = MASK[b * Ss + j0 + tid] ? SENT[b * Ss + j0 + tid] : 0.0f;
        }
        __syncthreads();

        if (t + 1 < NTL) {
            const char* kg = (const char*)(K + (head_off + j0 + KN) * Dd);
            const char* vg = (const char*)(V + (head_off + j0 + KN) * Dd);
            #pragma unroll
            for (int u = 0; u < 8; u++) {
                int i = u * TPB + tid;
                cp16(sb + SM_RAWK + i * 16, kg + i * 16);
                cp16(sb + SM_RAWV + i * 16, vg + i * 16);
            }
            CP_COMMIT();
        }

        // ---- QK (qh·kh + qh·kl, two depth-4 chains) + normalized epilogue ----
        uint32_t pah[8][4];
        #pragma unroll
        for (int nb = 0; nb < 16; nb++) {
            float sa[4] = {0.f, 0.f, 0.f, 0.f};
            float sbx[4] = {0.f, 0.f, 0.f, 0.f};
            uint32_t bh[8], bl[8];
            uint32_t rB = (uint32_t)(nb * 8 + (lane & 7)) * 128;
            uint32_t ch = (uint32_t)(lane >> 3) * 16;
            ldsm4(bh,     sb + SM_KH + sw128(rB + ch));
            ldsm4(bh + 4, sb + SM_KH + sw128(rB + ch + 64));
            ldsm4(bl,     sb + SM_KL + sw128(rB + ch));
            ldsm4(bl + 4, sb + SM_KL + sw128(rB + ch + 64));
            #pragma unroll
            for (int kb = 0; kb < 4; kb++) {
                mma16816(sa,  qh[kb], bh[2 * kb], bh[2 * kb + 1]);
                mma16816(sbx, qh[kb], bl[2 * kb], bl[2 * kb + 1]);
            }
            float2 s2 = *(float2*)&sentm[nb * 8 + cb];
            float p0 = __expf(sa[0] + sbx[0]) * s2.x * inv0;
            float p1 = __expf(sa[1] + sbx[1]) * s2.y * inv0;
            float p2 = __expf(sa[2] + sbx[2]) * s2.x * inv1;
            float p3 = __expf(sa[3] + sbx[3]) * s2.y * inv1;
            *(float2*)(arow0 + j0 + nb * 8 + cb) = make_float2(p0, p1);
            *(float2*)(arow1 + j0 + nb * 8 + cb) = make_float2(p2, p3);
            const int kb = nb >> 1, hf = (nb & 1) * 2;
            pah[kb][hf]     = cvt2h(p0, p1);
            pah[kb][hf + 1] = cvt2h(p2, p3);
        }

        // ---- PV: p·(vh + vl) ----
        #pragma unroll
        for (int kb = 0; kb < 8; kb++) {
            uint32_t vh[16], vl[16];
            uint32_t rV = (uint32_t)(kb * 16 + (lane & 15)) * 128;
            uint32_t chv = (uint32_t)(lane >> 4) * 16;
            #pragma unroll
            for (int qd = 0; qd < 4; qd++) {
                ldsm4t(vh + 4 * qd, sb + SM_VH + sw128(rV + chv + qd * 32));
                ldsm4t(vl + 4 * qd, sb + SM_VL + sw128(rV + chv + qd * 32));
            }
            #pragma unroll
            for (int nb = 0; nb < 8; nb++) {
                mma16816(oacc[nb], pah[kb], vh[2 * nb], vh[2 * nb + 1]);
                mma16816(oacc[nb], pah[kb], vl[2 * nb], vl[2 * nb + 1]);
            }
        }

        if (t + 1 < NTL) CP_WAIT0();
        __syncthreads();
    }

    // ---- write out (already normalized) ----
    {
        float2* o0 = (float2*)(OUT + (head_off + q0 + row0) * (size_t)Dd);
        float2* o1 = (float2*)(OUT + (head_off + q0 + row0 + 8) * (size_t)Dd);
        #pragma unroll
        for (int nb = 0; nb < 8; nb++) {
            o0[nb * 4 + (lane & 3)] = make_float2(oacc[nb][0], oacc[nb][1]);
            o1[nb * 4 + (lane & 3)] = make_float2(oacc[nb][2], oacc[nb][3]);
        }
    }
}

extern "C" void kernel_launch(void* const* d_in, const int* in_sizes, int n_in,
                              void* d_out, int out_size)
{
    const float* q    = (const float*)d_in[0];
    const float* k    = (const float*)d_in[1];
    const float* v    = (const float*)d_in[2];
    const float* sent = (const float*)d_in[3];
    const int*   mask = (const int*)d_in[4];

    float* out  = (float*)d_out;                    // [B,H,S,D]
    float* attn = out + (size_t)Bb * Hh * Ss * Dd;  // [B,H,S,S]

    cudaFuncSetAttribute(attn_kernel, cudaFuncAttributeMaxDynamicSharedMemorySize, SMEM_BYTES);

    dim3 grid(Ss / MT, Bb * Hh);
    attn_kernel<<<grid, TPB, SMEM_BYTES>>>(q, k, v, sent, mask, out, attn);
}

// round 10
// speedup vs baseline: 2.7407x; 1.3499x over previous
#include <cuda_runtime.h>
#include <cuda_fp16.h>
#include <cstdint>
#include <math.h>

#define Bb 2
#define Hh 16
#define Ss 2048
#define Dd 64
#define MT 256
#define KN 128
#define NTL (Ss/KN)
#define TPB 256
#define INV_TEMP 0.125f

// SMEM byte offsets
#define SM_QH 0
#define SM_KH 32768
#define SM_KL 49152
#define SM_VH 65536
#define SM_VL 81920
#define SM_RAWK 98304
#define SM_RAWV 131072
#define SM_SENT 163840
#define SMEM_BYTES 164352

__device__ __forceinline__ uint32_t smem_u32(const void* p) {
    uint32_t a; asm("{ .reg .u64 t; cvta.to.shared.u64 t, %1; cvt.u32.u64 %0, t; }" : "=r"(a) : "l"(p));
    return a;
}
__device__ __forceinline__ uint32_t sw128(uint32_t off) { return off ^ ((off >> 3) & 0x70); }

__device__ __forceinline__ uint32_t cvt2h(float x0, float x1) {
    __half2 H = __floats2half2_rn(x0, x1);
    return *(uint32_t*)&H;
}
__device__ __forceinline__ void split2h(float x0, float x1, uint32_t& hi, uint32_t& lo) {
    __half2 H = __floats2half2_rn(x0, x1);
    float r0 = x0 - __low2float(H), r1 = x1 - __high2float(H);
    __half2 L = __floats2half2_rn(r0, r1);
    hi = *(uint32_t*)&H; lo = *(uint32_t*)&L;
}

__device__ __forceinline__ void ldsm4(uint32_t* r, uint32_t addr) {
    asm volatile("ldmatrix.sync.aligned.m8n8.x4.shared.b16 {%0,%1,%2,%3}, [%4];"
        : "=r"(r[0]), "=r"(r[1]), "=r"(r[2]), "=r"(r[3]) : "r"(addr));
}
__device__ __forceinline__ void ldsm4t(uint32_t* r, uint32_t addr) {
    asm volatile("ldmatrix.sync.aligned.m8n8.x4.trans.shared.b16 {%0,%1,%2,%3}, [%4];"
        : "=r"(r[0]), "=r"(r[1]), "=r"(r[2]), "=r"(r[3]) : "r"(addr));
}
// non-volatile: register deps carry correctness, lets ptxas interleave chains
__device__ __forceinline__ void mma16816(float* c, const uint32_t* a, uint32_t b0, uint32_t b1) {
    asm("mma.sync.aligned.m16n8k16.row.col.f32.f16.f16.f32 "
        "{%0,%1,%2,%3}, {%4,%5,%6,%7}, {%8,%9}, {%0,%1,%2,%3};"
        : "+f"(c[0]), "+f"(c[1]), "+f"(c[2]), "+f"(c[3])
        : "r"(a[0]), "r"(a[1]), "r"(a[2]), "r"(a[3]), "r"(b0), "r"(b1));
}
__device__ __forceinline__ void cp16(uint32_t saddr, const void* g) {
    asm volatile("cp.async.ca.shared.global [%0], [%1], 16;" :: "r"(saddr), "l"(g));
}
#define CP_COMMIT() asm volatile("cp.async.commit_group;" ::: "memory")
#define CP_WAIT0()  asm volatile("cp.async.wait_group 0;" ::: "memory")

__global__ void __launch_bounds__(TPB, 1)
attn_kernel(const float* __restrict__ Q, const float* __restrict__ K,
            const float* __restrict__ V, const float* __restrict__ SENT,
            const int* __restrict__ MASK,
            float* __restrict__ OUT, float* __restrict__ ATTN)
{
    extern __shared__ char sm[];
    const uint32_t sb = smem_u32(sm);
    const int tid = threadIdx.x, lane = tid & 31, wid = tid >> 5;
    const int q0 = blockIdx.x * MT;
    const int head = blockIdx.y;
    const int b = head >> 4;
    const size_t head_off = (size_t)head * Ss;

    float* sentm = (float*)(sm + SM_SENT);

    // ---- stage Q (256 rows) -> fp16, pre-scaled, swizzled ----
    {
        const float4* qg = (const float4*)(Q + (head_off + q0) * Dd);
        #pragma unroll
        for (int u = 0; u < 8; u++) {
            int idx = u * TPB + tid;
            int r = idx >> 3, c = idx & 7;
            float4 a = qg[r * 16 + c * 2], bq = qg[r * 16 + c * 2 + 1];
            uint4 H;
            H.x = cvt2h(a.x * INV_TEMP, a.y * INV_TEMP);
            H.y = cvt2h(a.z * INV_TEMP, a.w * INV_TEMP);
            H.z = cvt2h(bq.x * INV_TEMP, bq.y * INV_TEMP);
            H.w = cvt2h(bq.z * INV_TEMP, bq.w * INV_TEMP);
            *(uint4*)(sm + SM_QH + sw128((uint32_t)(r * 128 + c * 16))) = H;
        }
    }
    // prefetch raw K tile 0
    {
        const char* kg = (const char*)(K + head_off * Dd);
        #pragma unroll
        for (int u = 0; u < 8; u++) {
            int i = u * TPB + tid;
            cp16(sb + SM_RAWK + i * 16, kg + i * 16);
        }
        CP_COMMIT();
    }
    __syncthreads();

    // ---- Q fragments: two m16 row-tiles per warp ----
    uint32_t qh[2][4][4];
    #pragma unroll
    for (int rs = 0; rs < 2; rs++) {
        uint32_t rowq = (uint32_t)(wid * 32 + rs * 16 + (lane & 15));
        #pragma unroll
        for (int kb = 0; kb < 4; kb++)
            ldsm4(qh[rs][kb], sb + SM_QH + sw128(rowq * 128 + ((uint32_t)(lane >> 4) + 2 * kb) * 16));
    }
    CP_WAIT0();
    __syncthreads();

    const int cb = 2 * (lane & 3);
    float rsum[2][2] = {{0.f, 0.f}, {0.f, 0.f}};

    // ================= Pass A: rowsums only (qh·kh) =================
    for (int t = 0; t < NTL; t++) {
        const int j0 = t * KN;
        {
            const float4* rk = (const float4*)(sm + SM_RAWK);
            #pragma unroll
            for (int u = 0; u < 4; u++) {
                int idx = u * TPB + tid;
                int r = idx >> 3, c = idx & 7;
                float4 a = rk[r * 16 + c * 2], bq = rk[r * 16 + c * 2 + 1];
                uint4 H;
                H.x = cvt2h(a.x, a.y);  H.y = cvt2h(a.z, a.w);
                H.z = cvt2h(bq.x, bq.y); H.w = cvt2h(bq.z, bq.w);
                *(uint4*)(sm + SM_KH + sw128((uint32_t)(r * 128 + c * 16))) = H;
            }
            if (tid < KN)
                sentm[tid] = MASK[b * Ss + j0 + tid] ? SENT[b * Ss + j0 + tid] : 0.0f;
        }
        __syncthreads();
        if (t + 1 < NTL) {
            const char* kg = (const char*)(K + (head_off + j0 + KN) * Dd);
            #pragma unroll
            for (int u = 0; u < 8; u++) {
                int i = u * TPB + tid;
                cp16(sb + SM_RAWK + i * 16, kg + i * 16);
            }
            CP_COMMIT();
        }
        #pragma unroll
        for (int nb = 0; nb < 16; nb++) {
            uint32_t bh[8];
            uint32_t rB = (uint32_t)(nb * 8 + (lane & 7)) * 128;
            uint32_t ch = (uint32_t)(lane >> 3) * 16;
            ldsm4(bh,     sb + SM_KH + sw128(rB + ch));
            ldsm4(bh + 4, sb + SM_KH + sw128(rB + ch + 64));
            float2 s2 = *(float2*)&sentm[nb * 8 + cb];
            #pragma unroll
            for (int rs = 0; rs < 2; rs++) {
                float sacc[4] = {0.f, 0.f, 0.f, 0.f};
                #pragma unroll
                for (int kb = 0; kb < 4; kb++)
                    mma16816(sacc, qh[rs][kb], bh[2 * kb], bh[2 * kb + 1]);
                rsum[rs][0] += __expf(sacc[0]) * s2.x + __expf(sacc[1]) * s2.y;
                rsum[rs][1] += __expf(sacc[2]) * s2.x + __expf(sacc[3]) * s2.y;
            }
        }
        if (t + 1 < NTL) CP_WAIT0();
        __syncthreads();
    }

    // ---- rowsum reduce within quads ----
    float inv[2][2];
    #pragma unroll
    for (int rs = 0; rs < 2; rs++)
        #pragma unroll
        for (int hrow = 0; hrow < 2; hrow++) {
            float r = rsum[rs][hrow];
            r += __shfl_xor_sync(0xFFFFFFFFu, r, 1);
            r += __shfl_xor_sync(0xFFFFFFFFu, r, 2);
            inv[rs][hrow] = 1.0f / r;
        }

    // prefetch raw K,V tile 0 for pass B
    {
        const char* kg = (const char*)(K + head_off * Dd);
        const char* vg = (const char*)(V + head_off * Dd);
        #pragma unroll
        for (int u = 0; u < 8; u++) {
            int i = u * TPB + tid;
            cp16(sb + SM_RAWK + i * 16, kg + i * 16);
            cp16(sb + SM_RAWV + i * 16, vg + i * 16);
        }
        CP_COMMIT();
        CP_WAIT0();
    }
    __syncthreads();

    float oacc[2][8][4];
    #pragma unroll
    for (int rs = 0; rs < 2; rs++)
        #pragma unroll
        for (int nb = 0; nb < 8; nb++)
            #pragma unroll
            for (int i = 0; i < 4; i++) oacc[rs][nb][i] = 0.f;

    float* arow[2][2];
    #pragma unroll
    for (int rs = 0; rs < 2; rs++) {
        int row0 = wid * 32 + rs * 16 + (lane >> 2);
        arow[rs][0] = ATTN + (head_off + q0 + row0) * (size_t)Ss;
        arow[rs][1] = arow[rs][0] + 8 * (size_t)Ss;
    }

    // ================= Pass B: normalized attn + PV (interleaved per 16 keys) =================
    for (int t = 0; t < NTL; t++) {
        const int j0 = t * KN;
        {   // convert K (hi/lo) and V (hi/lo)
            const float4* rk = (const float4*)(sm + SM_RAWK);
            const float4* rv = (const float4*)(sm + SM_RAWV);
            #pragma unroll
            for (int u = 0; u < 4; u++) {
                int idx = u * TPB + tid;
                int r = idx >> 3, c = idx & 7;
                uint32_t off = sw128((uint32_t)(r * 128 + c * 16));
                float4 a = rk[r * 16 + c * 2], bq = rk[r * 16 + c * 2 + 1];
                uint4 H, L;
                split2h(a.x, a.y, H.x, L.x);  split2h(a.z, a.w, H.y, L.y);
                split2h(bq.x, bq.y, H.z, L.z); split2h(bq.z, bq.w, H.w, L.w);
                *(uint4*)(sm + SM_KH + off) = H;
                *(uint4*)(sm + SM_KL + off) = L;
                a = rv[r * 16 + c * 2]; bq = rv[r * 16 + c * 2 + 1];
                split2h(a.x, a.y, H.x, L.x);  split2h(a.z, a.w, H.y, L.y);
                split2h(bq.x, bq.y, H.z, L.z); split2h(bq.z, bq.w, H.w, L.w);
                *(uint4*)(sm + SM_VH + off) = H;
                *(uint4*)(sm + SM_VL + off) = L;
            }
            if (tid < KN)
                sentm[tid] = MASK[b * Ss + j0 + tid] ? SENT[b * Ss + j0 + tid] : 0.0f;
        }
        __syncthreads();

        if (t + 1 < NTL) {
            const char* kg = (const char*)(K + (head_off + j0 + KN) * Dd);
            const char* vg = (const char*)(V + (head_off + j0 + KN) * Dd);
            #pragma unroll
            for (int u = 0; u < 8; u++) {
                int i = u * TPB + tid;
                cp16(sb + SM_RAWK + i * 16, kg + i * 16);
                cp16(sb + SM_RAWV + i * 16, vg + i * 16);
            }
            CP_COMMIT();
        }

        // ---- per 16-key block: QK -> p -> PV ----
        #pragma unroll
        for (int kb = 0; kb < 8; kb++) {
            uint32_t pa[2][4];           // p fragments for this key-block, both rowsets
            #pragma unroll
            for (int nbi = 0; nbi < 2; nbi++) {
                const int nb = 2 * kb + nbi;
                uint32_t bh[8], bl[8];
                uint32_t rB = (uint32_t)(nb * 8 + (lane & 7)) * 128;
                uint32_t ch = (uint32_t)(lane >> 3) * 16;
                ldsm4(bh,     sb + SM_KH + sw128(rB + ch));
                ldsm4(bh + 4, sb + SM_KH + sw128(rB + ch + 64));
                ldsm4(bl,     sb + SM_KL + sw128(rB + ch));
                ldsm4(bl + 4, sb + SM_KL + sw128(rB + ch + 64));
                float2 s2 = *(float2*)&sentm[nb * 8 + cb];
                #pragma unroll
                for (int rs = 0; rs < 2; rs++) {
                    float sa[4] = {0.f, 0.f, 0.f, 0.f};
                    float sx[4] = {0.f, 0.f, 0.f, 0.f};
                    #pragma unroll
                    for (int kd = 0; kd < 4; kd++) {
                        mma16816(sa, qh[rs][kd], bh[2 * kd], bh[2 * kd + 1]);
                        mma16816(sx, qh[rs][kd], bl[2 * kd], bl[2 * kd + 1]);
                    }
                    float p0 = __expf(sa[0] + sx[0]) * s2.x * inv[rs][0];
                    float p1 = __expf(sa[1] + sx[1]) * s2.y * inv[rs][0];
                    float p2 = __expf(sa[2] + sx[2]) * s2.x * inv[rs][1];
                    float p3 = __expf(sa[3] + sx[3]) * s2.y * inv[rs][1];
                    *(float2*)(arow[rs][0] + j0 + nb * 8 + cb) = make_float2(p0, p1);
                    *(float2*)(arow[rs][1] + j0 + nb * 8 + cb) = make_float2(p2, p3);
                    pa[rs][nbi * 2]     = cvt2h(p0, p1);
                    pa[rs][nbi * 2 + 1] = cvt2h(p2, p3);
                }
            }
            // PV for this key-block
            uint32_t vh[16], vl[16];
            uint32_t rV = (uint32_t)(kb * 16 + (lane & 15)) * 128;
            uint32_t chv = (uint32_t)(lane >> 4) * 16;
            #pragma unroll
            for (int qd = 0; qd < 4; qd++) {
                ldsm4t(vh + 4 * qd, sb + SM_VH + sw128(rV + chv + qd * 32));
                ldsm4t(vl + 4 * qd, sb + SM_VL + sw128(rV + chv + qd * 32));
            }
            #pragma unroll
            for (int rs = 0; rs < 2; rs++)
                #pragma unroll
                for (int nbd = 0; nbd < 8; nbd++) {
                    mma16816(oacc[rs][nbd], pa[rs], vh[2 * nbd], vh[2 * nbd + 1]);
                    mma16816(oacc[rs][nbd], pa[rs], vl[2 * nbd], vl[2 * nbd + 1]);
                }
        }

        if (t + 1 < NTL) CP_WAIT0();
        __syncthreads();
    }

    // ---- write out (already normalized) ----
    #pragma unroll
    for (int rs = 0; rs < 2; rs++) {
        int row0 = wid * 32 + rs * 16 + (lane >> 2);
        float2* o0 = (float2*)(OUT + (head_off + q0 + row0) * (size_t)Dd);
        float2* o1 = (float2*)(OUT + (head_off + q0 + row0 + 8) * (size_t)Dd);
        #pragma unroll
        for (int nbd = 0; nbd < 8; nbd++) {
            o0[nbd * 4 + (lane & 3)] = make_float2(oacc[rs][nbd][0], oacc[rs][nbd][1]);
            o1[nbd * 4 + (lane & 3)] = make_float2(oacc[rs][nbd][2], oacc[rs][nbd][3]);
        }
    }
}

extern "C" void kernel_launch(void* const* d_in, const int* in_sizes, int n_in,
                              void* d_out, int out_size)
{
    const float* q    = (const float*)d_in[0];
    const float* k    = (const float*)d_in[1];
    const float* v    = (const float*)d_in[2];
    const float* sent = (const float*)d_in[3];
    const int*   mask = (const int*)d_in[4];

    float* out  = (float*)d_out;                    // [B,H,S,D]
    float* attn = out + (size_t)Bb * Hh * Ss * Dd;  // [B,H,S,S]

    cudaFuncSetAttribute(attn_kernel, cudaFuncAttributeMaxDynamicSharedMemorySize, SMEM_BYTES);

    dim3 grid(Ss / MT, Bb * Hh);
    attn_kernel<<<grid, TPB, SMEM_BYTES>>>(q, k, v, sent, mask, out, attn);
}

// round 11
// speedup vs baseline: 2.9084x; 1.0612x over previous
#include <cuda_runtime.h>
#include <cuda_fp16.h>
#include <cstdint>
#include <math.h>

#define Bb 2
#define Hh 16
#define Ss 2048
#define Dd 64
#define MT 256
#define KN 128
#define NTL (Ss/KN)
#define TPB 256
#define INV_TEMP 0.125f

// scratch: [tensor(K=0,V=1)][head 0..31][tile 0..15][hi 16KB | lo 16KB]
#define SCR_TILE 32768
#define SCR_HEAD (NTL*SCR_TILE)            // 524288
#define SCR_TENSOR (32*SCR_HEAD)           // 16777216
__device__ __align__(16) unsigned char g_scr[2u * SCR_TENSOR];

// SMEM byte offsets
#define SM_QH 0
#define SM_BUF0 32768
#define SM_BUF1 98304
#define SM_SENT 163840                     // 2 x 128 floats (double buffered)
#define SMEM_BYTES 164864

__device__ __forceinline__ uint32_t smem_u32(const void* p) {
    uint32_t a; asm("{ .reg .u64 t; cvta.to.shared.u64 t, %1; cvt.u32.u64 %0, t; }" : "=r"(a) : "l"(p));
    return a;
}
__device__ __forceinline__ uint32_t sw128(uint32_t off) { return off ^ ((off >> 3) & 0x70); }

__device__ __forceinline__ uint32_t cvt2h(float x0, float x1) {
    __half2 H = __floats2half2_rn(x0, x1);
    return *(uint32_t*)&H;
}
__device__ __forceinline__ void split2h(float x0, float x1, uint32_t& hi, uint32_t& lo) {
    __half2 H = __floats2half2_rn(x0, x1);
    float r0 = x0 - __low2float(H), r1 = x1 - __high2float(H);
    __half2 L = __floats2half2_rn(r0, r1);
    hi = *(uint32_t*)&H; lo = *(uint32_t*)&L;
}

__device__ __forceinline__ void ldsm4(uint32_t* r, uint32_t addr) {
    asm volatile("ldmatrix.sync.aligned.m8n8.x4.shared.b16 {%0,%1,%2,%3}, [%4];"
        : "=r"(r[0]), "=r"(r[1]), "=r"(r[2]), "=r"(r[3]) : "r"(addr));
}
__device__ __forceinline__ void ldsm4t(uint32_t* r, uint32_t addr) {
    asm volatile("ldmatrix.sync.aligned.m8n8.x4.trans.shared.b16 {%0,%1,%2,%3}, [%4];"
        : "=r"(r[0]), "=r"(r[1]), "=r"(r[2]), "=r"(r[3]) : "r"(addr));
}
// non-volatile: register deps carry correctness, lets ptxas interleave chains
__device__ __forceinline__ void mma16816(float* c, const uint32_t* a, uint32_t b0, uint32_t b1) {
    asm("mma.sync.aligned.m16n8k16.row.col.f32.f16.f16.f32 "
        "{%0,%1,%2,%3}, {%4,%5,%6,%7}, {%8,%9}, {%0,%1,%2,%3};"
        : "+f"(c[0]), "+f"(c[1]), "+f"(c[2]), "+f"(c[3])
        : "r"(a[0]), "r"(a[1]), "r"(a[2]), "r"(a[3]), "r"(b0), "r"(b1));
}
__device__ __forceinline__ void cp16(uint32_t saddr, const void* g) {
    asm volatile("cp.async.ca.shared.global [%0], [%1], 16;" :: "r"(saddr), "l"(g));
}
#define CP_COMMIT() asm volatile("cp.async.commit_group;" ::: "memory")
#define CP_WAIT0()  asm volatile("cp.async.wait_group 0;" ::: "memory")
#define CP_WAIT1()  asm volatile("cp.async.wait_group 1;" ::: "memory")

// ---------- pre-kernel: split K,V into fp16 hi/lo in swizzled tile layout ----------
__global__ void __launch_bounds__(256, 4)
conv_kernel(const float* __restrict__ K, const float* __restrict__ V)
{
    const int idx = blockIdx.x * 256 + threadIdx.x;   // 0 .. 2*524288-1
    const int tensor = idx >> 19;
    const int c = idx & 524287;                        // chunk within tensor
    const int h = c >> 14;                             // 16384 chunks per head
    const int rem = c & 16383;
    const int j = rem >> 3, cc = rem & 7;
    const float* src = (tensor ? V : K) + (((size_t)h * Ss + j) * Dd) + cc * 8;
    float4 a = *(const float4*)src;
    float4 b2 = *(const float4*)(src + 4);
    uint4 H, L;
    split2h(a.x, a.y, H.x, L.x);   split2h(a.z, a.w, H.y, L.y);
    split2h(b2.x, b2.y, H.z, L.z); split2h(b2.z, b2.w, H.w, L.w);
    size_t base = (size_t)tensor * SCR_TENSOR + (size_t)h * SCR_HEAD + (size_t)(j >> 7) * SCR_TILE;
    uint32_t off = sw128((uint32_t)((j & 127) * 128 + cc * 16));
    *(uint4*)(g_scr + base + off) = H;
    *(uint4*)(g_scr + base + 16384 + off) = L;
}

__global__ void __launch_bounds__(TPB, 1)
attn_kernel(const float* __restrict__ Q, const float* __restrict__ SENT,
            const int* __restrict__ MASK,
            float* __restrict__ OUT, float* __restrict__ ATTN)
{
    extern __shared__ char sm[];
    const uint32_t sb = smem_u32(sm);
    const int tid = threadIdx.x, lane = tid & 31, wid = tid >> 5;
    const int q0 = blockIdx.x * MT;
    const int head = blockIdx.y;
    const int b = head >> 4;
    const size_t head_off = (size_t)head * Ss;

    const unsigned char* scrK = g_scr + (size_t)head * SCR_HEAD;
    const unsigned char* scrV = scrK + SCR_TENSOR;
    float* sentm = (float*)(sm + SM_SENT);
    const uint32_t bufb[2] = {sb + SM_BUF0, sb + SM_BUF1};

    // ---- stage Q (256 rows) -> fp16, pre-scaled, swizzled ----
    {
        const float4* qg = (const float4*)(Q + (head_off + q0) * Dd);
        #pragma unroll
        for (int u = 0; u < 8; u++) {
            int idx = u * TPB + tid;
            int r = idx >> 3, c = idx & 7;
            float4 a = qg[r * 16 + c * 2], bq = qg[r * 16 + c * 2 + 1];
            uint4 H;
            H.x = cvt2h(a.x * INV_TEMP, a.y * INV_TEMP);
            H.y = cvt2h(a.z * INV_TEMP, a.w * INV_TEMP);
            H.z = cvt2h(bq.x * INV_TEMP, bq.y * INV_TEMP);
            H.w = cvt2h(bq.z * INV_TEMP, bq.w * INV_TEMP);
            *(uint4*)(sm + SM_QH + sw128((uint32_t)(r * 128 + c * 16))) = H;
        }
    }
    // issue K-hi tile 0 for pass A
    {
        const unsigned char* s = scrK;
        #pragma unroll
        for (int u = 0; u < 4; u++) {
            int i = (u * TPB + tid) * 16;
            cp16(bufb[0] + i, s + i);
        }
        CP_COMMIT();
    }
    __syncthreads();

    // ---- Q fragments: two m16 row-tiles per warp ----
    uint32_t qh[2][4][4];
    #pragma unroll
    for (int rs = 0; rs < 2; rs++) {
        uint32_t rowq = (uint32_t)(wid * 32 + rs * 16 + (lane & 15));
        #pragma unroll
        for (int kb = 0; kb < 4; kb++)
            ldsm4(qh[rs][kb], sb + SM_QH + sw128(rowq * 128 + ((uint32_t)(lane >> 4) + 2 * kb) * 16));
    }

    const int cb = 2 * (lane & 3);
    float rsum[2][2] = {{0.f, 0.f}, {0.f, 0.f}};

    // ================= Pass A: rowsums only (qh·kh) =================
    for (int t = 0; t < NTL; t++) {
        if (t + 1 < NTL) {
            const unsigned char* s = scrK + (size_t)(t + 1) * SCR_TILE;
            #pragma unroll
            for (int u = 0; u < 4; u++) {
                int i = (u * TPB + tid) * 16;
                cp16(bufb[(t + 1) & 1] + i, s + i);
            }
            CP_COMMIT();
        }
        if (tid < KN) {
            int j = t * KN + tid;
            sentm[(t & 1) * 128 + tid] = MASK[b * Ss + j] ? SENT[b * Ss + j] : 0.0f;
        }
        if (t + 1 < NTL) CP_WAIT1(); else CP_WAIT0();
        __syncthreads();

        const uint32_t kh_b = bufb[t & 1];
        const float* sm_s = sentm + (t & 1) * 128;
        #pragma unroll
        for (int nb = 0; nb < 16; nb++) {
            uint32_t bh[8];
            uint32_t rB = (uint32_t)(nb * 8 + (lane & 7)) * 128;
            uint32_t ch = (uint32_t)(lane >> 3) * 16;
            ldsm4(bh,     kh_b + sw128(rB + ch));
            ldsm4(bh + 4, kh_b + sw128(rB + ch + 64));
            float2 s2 = *(float2*)&sm_s[nb * 8 + cb];
            #pragma unroll
            for (int rs = 0; rs < 2; rs++) {
                float sacc[4] = {0.f, 0.f, 0.f, 0.f};
                #pragma unroll
                for (int kb = 0; kb < 4; kb++)
                    mma16816(sacc, qh[rs][kb], bh[2 * kb], bh[2 * kb + 1]);
                rsum[rs][0] += __expf(sacc[0]) * s2.x + __expf(sacc[1]) * s2.y;
                rsum[rs][1] += __expf(sacc[2]) * s2.x + __expf(sacc[3]) * s2.y;
            }
        }
        __syncthreads();
    }

    // ---- rowsum reduce within quads ----
    float inv[2][2];
    #pragma unroll
    for (int rs = 0; rs < 2; rs++)
        #pragma unroll
        for (int hrow = 0; hrow < 2; hrow++) {
            float r = rsum[rs][hrow];
            r += __shfl_xor_sync(0xFFFFFFFFu, r, 1);
            r += __shfl_xor_sync(0xFFFFFFFFu, r, 2);
            inv[rs][hrow] = 1.0f / r;
        }

    // issue K+V tile 0 for pass B (64KB: Khi|Klo|Vhi|Vlo)
    {
        const unsigned char* ks = scrK;
        const unsigned char* vs = scrV;
        #pragma unroll
        for (int u = 0; u < 8; u++) {
            int i = (u * TPB + tid) * 16;
            cp16(bufb[0] + i, ks + i);
            cp16(bufb[0] + 32768 + i, vs + i);
        }
        CP_COMMIT();
    }

    float oacc[2][8][4];
    #pragma unroll
    for (int rs = 0; rs < 2; rs++)
        #pragma unroll
        for (int nb = 0; nb < 8; nb++)
            #pragma unroll
            for (int i = 0; i < 4; i++) oacc[rs][nb][i] = 0.f;

    float* arow[2][2];
    #pragma unroll
    for (int rs = 0; rs < 2; rs++) {
        int row0 = wid * 32 + rs * 16 + (lane >> 2);
        arow[rs][0] = ATTN + (head_off + q0 + row0) * (size_t)Ss;
        arow[rs][1] = arow[rs][0] + 8 * (size_t)Ss;
    }

    // ================= Pass B: normalized attn + PV =================
    for (int t = 0; t < NTL; t++) {
        const int j0 = t * KN;
        if (t + 1 < NTL) {
            const unsigned char* ks = scrK + (size_t)(t + 1) * SCR_TILE;
            const unsigned char* vs = scrV + (size_t)(t + 1) * SCR_TILE;
            #pragma unroll
            for (int u = 0; u < 8; u++) {
                int i = (u * TPB + tid) * 16;
                cp16(bufb[(t + 1) & 1] + i, ks + i);
                cp16(bufb[(t + 1) & 1] + 32768 + i, vs + i);
            }
            CP_COMMIT();
        }
        if (tid < KN) {
            int j = j0 + tid;
            sentm[(t & 1) * 128 + tid] = MASK[b * Ss + j] ? SENT[b * Ss + j] : 0.0f;
        }
        if (t + 1 < NTL) CP_WAIT1(); else CP_WAIT0();
        __syncthreads();

        const uint32_t kh_b = bufb[t & 1];
        const uint32_t kl_b = kh_b + 16384;
        const uint32_t vh_b = kh_b + 32768;
        const uint32_t vl_b = kh_b + 49152;
        const float* sm_s = sentm + (t & 1) * 128;

        // ---- per 16-key block: QK -> p -> PV ----
        #pragma unroll
        for (int kb = 0; kb < 8; kb++) {
            uint32_t pa[2][4];
            #pragma unroll
            for (int nbi = 0; nbi < 2; nbi++) {
                const int nb = 2 * kb + nbi;
                uint32_t bh[8], bl[8];
                uint32_t rB = (uint32_t)(nb * 8 + (lane & 7)) * 128;
                uint32_t ch = (uint32_t)(lane >> 3) * 16;
                ldsm4(bh,     kh_b + sw128(rB + ch));
                ldsm4(bh + 4, kh_b + sw128(rB + ch + 64));
                ldsm4(bl,     kl_b + sw128(rB + ch));
                ldsm4(bl + 4, kl_b + sw128(rB + ch + 64));
                float2 s2 = *(float2*)&sm_s[nb * 8 + cb];
                #pragma unroll
                for (int rs = 0; rs < 2; rs++) {
                    float sa[4] = {0.f, 0.f, 0.f, 0.f};
                    float sx[4] = {0.f, 0.f, 0.f, 0.f};
                    #pragma unroll
                    for (int kd = 0; kd < 4; kd++) {
                        mma16816(sa, qh[rs][kd], bh[2 * kd], bh[2 * kd + 1]);
                        mma16816(sx, qh[rs][kd], bl[2 * kd], bl[2 * kd + 1]);
                    }
                    float p0 = __expf(sa[0] + sx[0]) * s2.x * inv[rs][0];
                    float p1 = __expf(sa[1] + sx[1]) * s2.y * inv[rs][0];
                    float p2 = __expf(sa[2] + sx[2]) * s2.x * inv[rs][1];
                    float p3 = __expf(sa[3] + sx[3]) * s2.y * inv[rs][1];
                    *(float2*)(arow[rs][0] + j0 + nb * 8 + cb) = make_float2(p0, p1);
                    *(float2*)(arow[rs][1] + j0 + nb * 8 + cb) = make_float2(p2, p3);
                    pa[rs][nbi * 2]     = cvt2h(p0, p1);
                    pa[rs][nbi * 2 + 1] = cvt2h(p2, p3);
                }
            }
            // PV for this key-block
            uint32_t vh[16], vl[16];
            uint32_t rV = (uint32_t)(kb * 16 + (lane & 15)) * 128;
            uint32_t chv = (uint32_t)(lane >> 4) * 16;
            #pragma unroll
            for (int qd = 0; qd < 4; qd++) {
                ldsm4t(vh + 4 * qd, vh_b + sw128(rV + chv + qd * 32));
                ldsm4t(vl + 4 * qd, vl_b + sw128(rV + chv + qd * 32));
            }
            #pragma unroll
            for (int rs = 0; rs < 2; rs++)
                #pragma unroll
                for (int nbd = 0; nbd < 8; nbd++) {
                    mma16816(oacc[rs][nbd], pa[rs], vh[2 * nbd], vh[2 * nbd + 1]);
                    mma16816(oacc[rs][nbd], pa[rs], vl[2 * nbd], vl[2 * nbd + 1]);
                }
        }
        __syncthreads();
    }

    // ---- write out (already normalized) ----
    #pragma unroll
    for (int rs = 0; rs < 2; rs++) {
        int row0 = wid * 32 + rs * 16 + (lane >> 2);
        float2* o0 = (float2*)(OUT + (head_off + q0 + row0) * (size_t)Dd);
        float2* o1 = (float2*)(OUT + (head_off + q0 + row0 + 8) * (size_t)Dd);
        #pragma unroll
        for (int nbd = 0; nbd < 8; nbd++) {
            o0[nbd * 4 + (lane & 3)] = make_float2(oacc[rs][nbd][0], oacc[rs][nbd][1]);
            o1[nbd * 4 + (lane & 3)] = make_float2(oacc[rs][nbd][2], oacc[rs][nbd][3]);
        }
    }
}

extern "C" void kernel_launch(void* const* d_in, const int* in_sizes, int n_in,
                              void* d_out, int out_size)
{
    const float* q    = (const float*)d_in[0];
    const float* k    = (const float*)d_in[1];
    const float* v    = (const float*)d_in[2];
    const float* sent = (const float*)d_in[3];
    const int*   mask = (const int*)d_in[4];

    float* out  = (float*)d_out;                    // [B,H,S,D]
    float* attn = out + (size_t)Bb * Hh * Ss * Dd;  // [B,H,S,S]

    conv_kernel<<<4096, 256>>>(k, v);

    cudaFuncSetAttribute(attn_kernel, cudaFuncAttributeMaxDynamicSharedMemorySize, SMEM_BYTES);
    dim3 grid(Ss / MT, Bb * Hh);
    attn_kernel<<<grid, TPB, SMEM_BYTES>>>(q, sent, mask, out, attn);
}

// round 12
// speedup vs baseline: 3.6922x; 1.2695x over previous
#include <cuda_runtime.h>
#include <cuda_fp16.h>
#include <cstdint>
#include <math.h>

#define Bb 2
#define Hh 16
#define Ss 2048
#define Dd 64
#define MT 256
#define KN 128
#define NTL (Ss/KN)
#define TPB 256
#define INV_TEMP 0.125f

// K scratch: [head][tile][hi 16KB | lo 16KB]; V scratch: [head][tile][hi 16KB]
#define SCRK_TILE 32768
#define SCRK_HEAD (NTL*SCRK_TILE)          // 524288
#define SCRK_TOTAL (32u*SCRK_HEAD)         // 16777216
#define SCRV_TILE 16384
#define SCRV_HEAD (NTL*SCRV_TILE)          // 262144
#define SCRV_TOTAL (32u*SCRV_HEAD)         // 8388608
__device__ __align__(16) unsigned char g_scr[SCRK_TOTAL + SCRV_TOTAL];
__device__ float g_rinv[32 * Ss];

// SMEM offsets (pass B)
#define SM_QH 0
#define SM_BUF0 32768
#define SM_BUF1 81920
#define SM_SENT 131072
#define SMEM_B_BYTES 132096
// SMEM offsets (pass A)
#define SA_BUF0 32768
#define SA_BUF1 49152
#define SA_SENT 65536
#define SMEM_A_BYTES 66560

__device__ __forceinline__ uint32_t smem_u32(const void* p) {
    uint32_t a; asm("{ .reg .u64 t; cvta.to.shared.u64 t, %1; cvt.u32.u64 %0, t; }" : "=r"(a) : "l"(p));
    return a;
}
__device__ __forceinline__ uint32_t sw128(uint32_t off) { return off ^ ((off >> 3) & 0x70); }

__device__ __forceinline__ uint32_t cvt2h(float x0, float x1) {
    __half2 H = __floats2half2_rn(x0, x1);
    return *(uint32_t*)&H;
}
__device__ __forceinline__ void split2h(float x0, float x1, uint32_t& hi, uint32_t& lo) {
    __half2 H = __floats2half2_rn(x0, x1);
    float r0 = x0 - __low2float(H), r1 = x1 - __high2float(H);
    __half2 L = __floats2half2_rn(r0, r1);
    hi = *(uint32_t*)&H; lo = *(uint32_t*)&L;
}

__device__ __forceinline__ void ldsm4(uint32_t* r, uint32_t addr) {
    asm volatile("ldmatrix.sync.aligned.m8n8.x4.shared.b16 {%0,%1,%2,%3}, [%4];"
        : "=r"(r[0]), "=r"(r[1]), "=r"(r[2]), "=r"(r[3]) : "r"(addr));
}
__device__ __forceinline__ void ldsm4t(uint32_t* r, uint32_t addr) {
    asm volatile("ldmatrix.sync.aligned.m8n8.x4.trans.shared.b16 {%0,%1,%2,%3}, [%4];"
        : "=r"(r[0]), "=r"(r[1]), "=r"(r[2]), "=r"(r[3]) : "r"(addr));
}
__device__ __forceinline__ void mma16816(float* c, const uint32_t* a, uint32_t b0, uint32_t b1) {
    asm("mma.sync.aligned.m16n8k16.row.col.f32.f16.f16.f32 "
        "{%0,%1,%2,%3}, {%4,%5,%6,%7}, {%8,%9}, {%0,%1,%2,%3};"
        : "+f"(c[0]), "+f"(c[1]), "+f"(c[2]), "+f"(c[3])
        : "r"(a[0]), "r"(a[1]), "r"(a[2]), "r"(a[3]), "r"(b0), "r"(b1));
}
__device__ __forceinline__ void cp16(uint32_t saddr, const void* g) {
    asm volatile("cp.async.ca.shared.global [%0], [%1], 16;" :: "r"(saddr), "l"(g));
}
#define CP_COMMIT() asm volatile("cp.async.commit_group;" ::: "memory")
#define CP_WAIT0()  asm volatile("cp.async.wait_group 0;" ::: "memory")
#define CP_WAIT1()  asm volatile("cp.async.wait_group 1;" ::: "memory")

// ---------- conv: K -> hi/lo, V -> hi only, swizzled tile layout ----------
__global__ void __launch_bounds__(256, 4)
conv_kernel(const float* __restrict__ K, const float* __restrict__ V)
{
    const int idx = blockIdx.x * 256 + threadIdx.x;
    const int tensor = idx >> 19;
    const int c = idx & 524287;
    const int h = c >> 14;
    const int rem = c & 16383;
    const int j = rem >> 3, cc = rem & 7;
    const float* src = (tensor ? V : K) + (((size_t)h * Ss + j) * Dd) + cc * 8;
    float4 a = *(const float4*)src;
    float4 b2 = *(const float4*)(src + 4);
    uint4 H, L;
    split2h(a.x, a.y, H.x, L.x);   split2h(a.z, a.w, H.y, L.y);
    split2h(b2.x, b2.y, H.z, L.z); split2h(b2.z, b2.w, H.w, L.w);
    uint32_t off = sw128((uint32_t)((j & 127) * 128 + cc * 16));
    if (tensor == 0) {
        size_t base = (size_t)h * SCRK_HEAD + (size_t)(j >> 7) * SCRK_TILE;
        *(uint4*)(g_scr + base + off) = H;
        *(uint4*)(g_scr + base + 16384 + off) = L;
    } else {
        size_t base = SCRK_TOTAL + (size_t)h * SCRV_HEAD + (size_t)(j >> 7) * SCRV_TILE;
        *(uint4*)(g_scr + base + off) = H;
    }
}

// ---------- pass A: rowsum inverses (qh·kh), 2 CTAs/SM ----------
__global__ void __launch_bounds__(256, 2)
passA_kernel(const float* __restrict__ Q, const float* __restrict__ SENT,
             const int* __restrict__ MASK)
{
    extern __shared__ char sm[];
    const uint32_t sb = smem_u32(sm);
    const int tid = threadIdx.x, lane = tid & 31, wid = tid >> 5;
    const int q0 = blockIdx.x * MT;
    const int head = blockIdx.y;
    const int b = head >> 4;
    const size_t head_off = (size_t)head * Ss;

    const unsigned char* scrK = g_scr + (size_t)head * SCRK_HEAD;
    float* sentm = (float*)(sm + SA_SENT);
    const uint32_t bufb[2] = {sb + SA_BUF0, sb + SA_BUF1};

    // stage Q -> fp16 pre-scaled swizzled
    {
        const float4* qg = (const float4*)(Q + (head_off + q0) * Dd);
        #pragma unroll
        for (int u = 0; u < 8; u++) {
            int idx = u * TPB + tid;
            int r = idx >> 3, c = idx & 7;
            float4 a = qg[r * 16 + c * 2], bq = qg[r * 16 + c * 2 + 1];
            uint4 H;
            H.x = cvt2h(a.x * INV_TEMP, a.y * INV_TEMP);
            H.y = cvt2h(a.z * INV_TEMP, a.w * INV_TEMP);
            H.z = cvt2h(bq.x * INV_TEMP, bq.y * INV_TEMP);
            H.w = cvt2h(bq.z * INV_TEMP, bq.w * INV_TEMP);
            *(uint4*)(sm + SM_QH + sw128((uint32_t)(r * 128 + c * 16))) = H;
        }
    }
    {   // K-hi tile 0
        #pragma unroll
        for (int u = 0; u < 4; u++) {
            int i = (u * TPB + tid) * 16;
            cp16(bufb[0] + i, scrK + i);
        }
        CP_COMMIT();
    }
    __syncthreads();

    uint32_t qh[2][4][4];
    #pragma unroll
    for (int rs = 0; rs < 2; rs++) {
        uint32_t rowq = (uint32_t)(wid * 32 + rs * 16 + (lane & 15));
        #pragma unroll
        for (int kb = 0; kb < 4; kb++)
            ldsm4(qh[rs][kb], sb + SM_QH + sw128(rowq * 128 + ((uint32_t)(lane >> 4) + 2 * kb) * 16));
    }

    const int cb = 2 * (lane & 3);
    float rsum[2][2] = {{0.f, 0.f}, {0.f, 0.f}};

    for (int t = 0; t < NTL; t++) {
        if (t + 1 < NTL) {
            const unsigned char* s = scrK + (size_t)(t + 1) * SCRK_TILE;
            #pragma unroll
            for (int u = 0; u < 4; u++) {
                int i = (u * TPB + tid) * 16;
                cp16(bufb[(t + 1) & 1] + i, s + i);
            }
            CP_COMMIT();
        }
        if (tid < KN) {
            int j = t * KN + tid;
            sentm[(t & 1) * 128 + tid] = MASK[b * Ss + j] ? SENT[b * Ss + j] : 0.0f;
        }
        if (t + 1 < NTL) CP_WAIT1(); else CP_WAIT0();
        __syncthreads();

        const uint32_t kh_b = bufb[t & 1];
        const float* sm_s = sentm + (t & 1) * 128;
        #pragma unroll
        for (int nb = 0; nb < 16; nb++) {
            uint32_t bh[8];
            uint32_t rB = (uint32_t)(nb * 8 + (lane & 7)) * 128;
            uint32_t ch = (uint32_t)(lane >> 3) * 16;
            ldsm4(bh,     kh_b + sw128(rB + ch));
            ldsm4(bh + 4, kh_b + sw128(rB + ch + 64));
            float2 s2 = *(float2*)&sm_s[nb * 8 + cb];
            #pragma unroll
            for (int rs = 0; rs < 2; rs++) {
                float sacc[4] = {0.f, 0.f, 0.f, 0.f};
                #pragma unroll
                for (int kb = 0; kb < 4; kb++)
                    mma16816(sacc, qh[rs][kb], bh[2 * kb], bh[2 * kb + 1]);
                rsum[rs][0] += __expf(sacc[0]) * s2.x + __expf(sacc[1]) * s2.y;
                rsum[rs][1] += __expf(sacc[2]) * s2.x + __expf(sacc[3]) * s2.y;
            }
        }
        __syncthreads();
    }

    #pragma unroll
    for (int rs = 0; rs < 2; rs++)
        #pragma unroll
        for (int hrow = 0; hrow < 2; hrow++) {
            float r = rsum[rs][hrow];
            r += __shfl_xor_sync(0xFFFFFFFFu, r, 1);
            r += __shfl_xor_sync(0xFFFFFFFFu, r, 2);
            if ((lane & 3) == 0)
                g_rinv[head * Ss + q0 + wid * 32 + rs * 16 + (lane >> 2) + hrow * 8] = 1.0f / r;
        }
}

// ---------- pass B: normalized attn + PV ----------
__global__ void __launch_bounds__(TPB, 1)
attn_kernel(const float* __restrict__ Q, const float* __restrict__ SENT,
            const int* __restrict__ MASK,
            float* __restrict__ OUT, float* __restrict__ ATTN)
{
    extern __shared__ char sm[];
    const uint32_t sb = smem_u32(sm);
    const int tid = threadIdx.x, lane = tid & 31, wid = tid >> 5;
    const int q0 = blockIdx.x * MT;
    const int head = blockIdx.y;
    const int b = head >> 4;
    const size_t head_off = (size_t)head * Ss;

    const unsigned char* scrK = g_scr + (size_t)head * SCRK_HEAD;
    const unsigned char* scrV = g_scr + SCRK_TOTAL + (size_t)head * SCRV_HEAD;
    float* sentm = (float*)(sm + SM_SENT);
    const uint32_t bufb[2] = {sb + SM_BUF0, sb + SM_BUF1};

    // stage Q
    {
        const float4* qg = (const float4*)(Q + (head_off + q0) * Dd);
        #pragma unroll
        for (int u = 0; u < 8; u++) {
            int idx = u * TPB + tid;
            int r = idx >> 3, c = idx & 7;
            float4 a = qg[r * 16 + c * 2], bq = qg[r * 16 + c * 2 + 1];
            uint4 H;
            H.x = cvt2h(a.x * INV_TEMP, a.y * INV_TEMP);
            H.y = cvt2h(a.z * INV_TEMP, a.w * INV_TEMP);
            H.z = cvt2h(bq.x * INV_TEMP, bq.y * INV_TEMP);
            H.w = cvt2h(bq.z * INV_TEMP, bq.w * INV_TEMP);
            *(uint4*)(sm + SM_QH + sw128((uint32_t)(r * 128 + c * 16))) = H;
        }
    }
    // tile 0: Khi|Klo|Vhi = 48KB
    {
        #pragma unroll
        for (int u = 0; u < 8; u++) {
            int i = (u * TPB + tid) * 16;
            cp16(bufb[0] + i, scrK + i);
        }
        #pragma unroll
        for (int u = 0; u < 4; u++) {
            int i = (u * TPB + tid) * 16;
            cp16(bufb[0] + 32768 + i, scrV + i);
        }
        CP_COMMIT();
    }
    __syncthreads();

    uint32_t qh[2][4][4];
    #pragma unroll
    for (int rs = 0; rs < 2; rs++) {
        uint32_t rowq = (uint32_t)(wid * 32 + rs * 16 + (lane & 15));
        #pragma unroll
        for (int kb = 0; kb < 4; kb++)
            ldsm4(qh[rs][kb], sb + SM_QH + sw128(rowq * 128 + ((uint32_t)(lane >> 4) + 2 * kb) * 16));
    }

    const int cb = 2 * (lane & 3);

    // load rowsum inverses from pass A
    float inv[2][2];
    float* arow[2][2];
    #pragma unroll
    for (int rs = 0; rs < 2; rs++) {
        int row0 = wid * 32 + rs * 16 + (lane >> 2);
        inv[rs][0] = g_rinv[head * Ss + q0 + row0];
        inv[rs][1] = g_rinv[head * Ss + q0 + row0 + 8];
        arow[rs][0] = ATTN + (head_off + q0 + row0) * (size_t)Ss;
        arow[rs][1] = arow[rs][0] + 8 * (size_t)Ss;
    }

    float oacc[2][8][4];
    #pragma unroll
    for (int rs = 0; rs < 2; rs++)
        #pragma unroll
        for (int nb = 0; nb < 8; nb++)
            #pragma unroll
            for (int i = 0; i < 4; i++) oacc[rs][nb][i] = 0.f;

    for (int t = 0; t < NTL; t++) {
        const int j0 = t * KN;
        if (t + 1 < NTL) {
            const unsigned char* ks = scrK + (size_t)(t + 1) * SCRK_TILE;
            const unsigned char* vs = scrV + (size_t)(t + 1) * SCRV_TILE;
            #pragma unroll
            for (int u = 0; u < 8; u++) {
                int i = (u * TPB + tid) * 16;
                cp16(bufb[(t + 1) & 1] + i, ks + i);
            }
            #pragma unroll
            for (int u = 0; u < 4; u++) {
                int i = (u * TPB + tid) * 16;
                cp16(bufb[(t + 1) & 1] + 32768 + i, vs + i);
            }
            CP_COMMIT();
        }
        if (tid < KN) {
            int j = j0 + tid;
            sentm[(t & 1) * 128 + tid] = MASK[b * Ss + j] ? SENT[b * Ss + j] : 0.0f;
        }
        if (t + 1 < NTL) CP_WAIT1(); else CP_WAIT0();
        __syncthreads();

        const uint32_t kh_b = bufb[t & 1];
        const uint32_t kl_b = kh_b + 16384;
        const uint32_t vh_b = kh_b + 32768;
        const float* sm_s = sentm + (t & 1) * 128;

        #pragma unroll
        for (int kb = 0; kb < 8; kb++) {
            uint32_t pa[2][4];
            #pragma unroll
            for (int nbi = 0; nbi < 2; nbi++) {
                const int nb = 2 * kb + nbi;
                uint32_t bh[8], bl[8];
                uint32_t rB = (uint32_t)(nb * 8 + (lane & 7)) * 128;
                uint32_t ch = (uint32_t)(lane >> 3) * 16;
                ldsm4(bh,     kh_b + sw128(rB + ch));
                ldsm4(bh + 4, kh_b + sw128(rB + ch + 64));
                ldsm4(bl,     kl_b + sw128(rB + ch));
                ldsm4(bl + 4, kl_b + sw128(rB + ch + 64));
                float2 s2 = *(float2*)&sm_s[nb * 8 + cb];
                #pragma unroll
                for (int rs = 0; rs < 2; rs++) {
                    float sa[4] = {0.f, 0.f, 0.f, 0.f};
                    float sx[4] = {0.f, 0.f, 0.f, 0.f};
                    #pragma unroll
                    for (int kd = 0; kd < 4; kd++) {
                        mma16816(sa, qh[rs][kd], bh[2 * kd], bh[2 * kd + 1]);
                        mma16816(sx, qh[rs][kd], bl[2 * kd], bl[2 * kd + 1]);
                    }
                    float p0 = __expf(sa[0] + sx[0]) * s2.x * inv[rs][0];
                    float p1 = __expf(sa[1] + sx[1]) * s2.y * inv[rs][0];
                    float p2 = __expf(sa[2] + sx[2]) * s2.x * inv[rs][1];
                    float p3 = __expf(sa[3] + sx[3]) * s2.y * inv[rs][1];
                    *(float2*)(arow[rs][0] + j0 + nb * 8 + cb) = make_float2(p0, p1);
                    *(float2*)(arow[rs][1] + j0 + nb * 8 + cb) = make_float2(p2, p3);
                    pa[rs][nbi * 2]     = cvt2h(p0, p1);
                    pa[rs][nbi * 2 + 1] = cvt2h(p2, p3);
                }
            }
            // PV (V-hi only)
            uint32_t vh[16];
            uint32_t rV = (uint32_t)(kb * 16 + (lane & 15)) * 128;
            uint32_t chv = (uint32_t)(lane >> 4) * 16;
            #pragma unroll
            for (int qd = 0; qd < 4; qd++)
                ldsm4t(vh + 4 * qd, vh_b + sw128(rV + chv + qd * 32));
            #pragma unroll
            for (int rs = 0; rs < 2; rs++)
                #pragma unroll
                for (int nbd = 0; nbd < 8; nbd++)
                    mma16816(oacc[rs][nbd], pa[rs], vh[2 * nbd], vh[2 * nbd + 1]);
        }
        __syncthreads();
    }

    // write out (already normalized)
    #pragma unroll
    for (int rs = 0; rs < 2; rs++) {
        int row0 = wid * 32 + rs * 16 + (lane >> 2);
        float2* o0 = (float2*)(OUT + (head_off + q0 + row0) * (size_t)Dd);
        float2* o1 = (float2*)(OUT + (head_off + q0 + row0 + 8) * (size_t)Dd);
        #pragma unroll
        for (int nbd = 0; nbd < 8; nbd++) {
            o0[nbd * 4 + (lane & 3)] = make_float2(oacc[rs][nbd][0], oacc[rs][nbd][1]);
            o1[nbd * 4 + (lane & 3)] = make_float2(oacc[rs][nbd][2], oacc[rs][nbd][3]);
        }
    }
}

extern "C" void kernel_launch(void* const* d_in, const int* in_sizes, int n_in,
                              void* d_out, int out_size)
{
    const float* q    = (const float*)d_in[0];
    const float* k    = (const float*)d_in[1];
    const float* v    = (const float*)d_in[2];
    const float* sent = (const float*)d_in[3];
    const int*   mask = (const int*)d_in[4];

    float* out  = (float*)d_out;                    // [B,H,S,D]
    float* attn = out + (size_t)Bb * Hh * Ss * Dd;  // [B,H,S,S]

    conv_kernel<<<4096, 256>>>(k, v);

    cudaFuncSetAttribute(passA_kernel, cudaFuncAttributeMaxDynamicSharedMemorySize, SMEM_A_BYTES);
    dim3 gridA(Ss / MT, Bb * Hh);
    passA_kernel<<<gridA, TPB, SMEM_A_BYTES>>>(q, sent, mask);

    cudaFuncSetAttribute(attn_kernel, cudaFuncAttributeMaxDynamicSharedMemorySize, SMEM_B_BYTES);
    dim3 gridB(Ss / MT, Bb * Hh);
    attn_kernel<<<gridB, TPB, SMEM_B_BYTES>>>(q, sent, mask, out, attn);
}

// round 13
// speedup vs baseline: 4.0225x; 1.0894x over previous
#include <cuda_runtime.h>
#include <cuda_fp16.h>
#include <cstdint>
#include <math.h>

#define Bb 2
#define Hh 16
#define Ss 2048
#define Dd 64
#define MT 256
#define KN 128
#define NTL (Ss/KN)
#define TPB 256
#define INV_TEMP 0.125f

// scratch: K-hi [head][tile 16KB], then V-hi [head][tile 16KB]
#define SCR_TILE 16384
#define SCR_HEAD (NTL*SCR_TILE)            // 262144
#define SCR_TENSOR (32u*SCR_HEAD)          // 8388608
__device__ __align__(16) unsigned char g_scr[2u * SCR_TENSOR];
__device__ float g_rinv[32 * Ss];

// SMEM offsets (pass B): QH 32K | BUF0 32K (Khi|Vhi) | BUF1 32K | SENT
#define SM_QH 0
#define SM_BUF0 32768
#define SM_BUF1 65536
#define SM_SENT 98304
#define SMEM_B_BYTES 99328
// SMEM offsets (pass A): QH 32K | BUF0 16K | BUF1 16K | SENT
#define SA_BUF0 32768
#define SA_BUF1 49152
#define SA_SENT 65536
#define SMEM_A_BYTES 66560

__device__ __forceinline__ uint32_t smem_u32(const void* p) {
    uint32_t a; asm("{ .reg .u64 t; cvta.to.shared.u64 t, %1; cvt.u32.u64 %0, t; }" : "=r"(a) : "l"(p));
    return a;
}
__device__ __forceinline__ uint32_t sw128(uint32_t off) { return off ^ ((off >> 3) & 0x70); }

__device__ __forceinline__ uint32_t cvt2h(float x0, float x1) {
    __half2 H = __floats2half2_rn(x0, x1);
    return *(uint32_t*)&H;
}

__device__ __forceinline__ void ldsm4(uint32_t* r, uint32_t addr) {
    asm volatile("ldmatrix.sync.aligned.m8n8.x4.shared.b16 {%0,%1,%2,%3}, [%4];"
        : "=r"(r[0]), "=r"(r[1]), "=r"(r[2]), "=r"(r[3]) : "r"(addr));
}
__device__ __forceinline__ void ldsm4t(uint32_t* r, uint32_t addr) {
    asm volatile("ldmatrix.sync.aligned.m8n8.x4.trans.shared.b16 {%0,%1,%2,%3}, [%4];"
        : "=r"(r[0]), "=r"(r[1]), "=r"(r[2]), "=r"(r[3]) : "r"(addr));
}
__device__ __forceinline__ void mma16816(float* c, const uint32_t* a, uint32_t b0, uint32_t b1) {
    asm("mma.sync.aligned.m16n8k16.row.col.f32.f16.f16.f32 "
        "{%0,%1,%2,%3}, {%4,%5,%6,%7}, {%8,%9}, {%0,%1,%2,%3};"
        : "+f"(c[0]), "+f"(c[1]), "+f"(c[2]), "+f"(c[3])
        : "r"(a[0]), "r"(a[1]), "r"(a[2]), "r"(a[3]), "r"(b0), "r"(b1));
}
__device__ __forceinline__ void cp16(uint32_t saddr, const void* g) {
    asm volatile("cp.async.ca.shared.global [%0], [%1], 16;" :: "r"(saddr), "l"(g));
}
#define CP_COMMIT() asm volatile("cp.async.commit_group;" ::: "memory")
#define CP_WAIT0()  asm volatile("cp.async.wait_group 0;" ::: "memory")
#define CP_WAIT1()  asm volatile("cp.async.wait_group 1;" ::: "memory")

// ---------- conv: K,V -> fp16 hi, swizzled tile layout ----------
__global__ void __launch_bounds__(256, 4)
conv_kernel(const float* __restrict__ K, const float* __restrict__ V)
{
    const int idx = blockIdx.x * 256 + threadIdx.x;
    const int tensor = idx >> 19;
    const int c = idx & 524287;
    const int h = c >> 14;
    const int rem = c & 16383;
    const int j = rem >> 3, cc = rem & 7;
    const float* src = (tensor ? V : K) + (((size_t)h * Ss + j) * Dd) + cc * 8;
    float4 a = *(const float4*)src;
    float4 b2 = *(const float4*)(src + 4);
    uint4 H;
    H.x = cvt2h(a.x, a.y);   H.y = cvt2h(a.z, a.w);
    H.z = cvt2h(b2.x, b2.y); H.w = cvt2h(b2.z, b2.w);
    size_t base = (size_t)tensor * SCR_TENSOR + (size_t)h * SCR_HEAD + (size_t)(j >> 7) * SCR_TILE;
    uint32_t off = sw128((uint32_t)((j & 127) * 128 + cc * 16));
    *(uint4*)(g_scr + base + off) = H;
}

// ---------- pass A: rowsum inverses (qh·kh), 2 CTAs/SM, single wave ----------
__global__ void __launch_bounds__(256, 2)
passA_kernel(const float* __restrict__ Q, const float* __restrict__ SENT,
             const int* __restrict__ MASK)
{
    extern __shared__ char sm[];
    const uint32_t sb = smem_u32(sm);
    const int tid = threadIdx.x, lane = tid & 31, wid = tid >> 5;
    const int q0 = blockIdx.x * MT;
    const int head = blockIdx.y;
    const int b = head >> 4;
    const size_t head_off = (size_t)head * Ss;

    const unsigned char* scrK = g_scr + (size_t)head * SCR_HEAD;
    float* sentm = (float*)(sm + SA_SENT);
    const uint32_t bufb[2] = {sb + SA_BUF0, sb + SA_BUF1};

    {
        const float4* qg = (const float4*)(Q + (head_off + q0) * Dd);
        #pragma unroll
        for (int u = 0; u < 8; u++) {
            int idx = u * TPB + tid;
            int r = idx >> 3, c = idx & 7;
            float4 a = qg[r * 16 + c * 2], bq = qg[r * 16 + c * 2 + 1];
            uint4 H;
            H.x = cvt2h(a.x * INV_TEMP, a.y * INV_TEMP);
            H.y = cvt2h(a.z * INV_TEMP, a.w * INV_TEMP);
            H.z = cvt2h(bq.x * INV_TEMP, bq.y * INV_TEMP);
            H.w = cvt2h(bq.z * INV_TEMP, bq.w * INV_TEMP);
            *(uint4*)(sm + SM_QH + sw128((uint32_t)(r * 128 + c * 16))) = H;
        }
    }
    {
        #pragma unroll
        for (int u = 0; u < 4; u++) {
            int i = (u * TPB + tid) * 16;
            cp16(bufb[0] + i, scrK + i);
        }
        CP_COMMIT();
    }
    __syncthreads();

    uint32_t qh[2][4][4];
    #pragma unroll
    for (int rs = 0; rs < 2; rs++) {
        uint32_t rowq = (uint32_t)(wid * 32 + rs * 16 + (lane & 15));
        #pragma unroll
        for (int kb = 0; kb < 4; kb++)
            ldsm4(qh[rs][kb], sb + SM_QH + sw128(rowq * 128 + ((uint32_t)(lane >> 4) + 2 * kb) * 16));
    }

    const int cb = 2 * (lane & 3);
    float rsum[2][2] = {{0.f, 0.f}, {0.f, 0.f}};

    for (int t = 0; t < NTL; t++) {
        if (t + 1 < NTL) {
            const unsigned char* s = scrK + (size_t)(t + 1) * SCR_TILE;
            #pragma unroll
            for (int u = 0; u < 4; u++) {
                int i = (u * TPB + tid) * 16;
                cp16(bufb[(t + 1) & 1] + i, s + i);
            }
            CP_COMMIT();
        }
        if (tid < KN) {
            int j = t * KN + tid;
            sentm[(t & 1) * 128 + tid] = MASK[b * Ss + j] ? SENT[b * Ss + j] : 0.0f;
        }
        if (t + 1 < NTL) CP_WAIT1(); else CP_WAIT0();
        __syncthreads();

        const uint32_t kh_b = bufb[t & 1];
        const float* sm_s = sentm + (t & 1) * 128;
        #pragma unroll
        for (int nb = 0; nb < 16; nb++) {
            uint32_t bh[8];
            uint32_t rB = (uint32_t)(nb * 8 + (lane & 7)) * 128;
            uint32_t ch = (uint32_t)(lane >> 3) * 16;
            ldsm4(bh,     kh_b + sw128(rB + ch));
            ldsm4(bh + 4, kh_b + sw128(rB + ch + 64));
            float2 s2 = *(float2*)&sm_s[nb * 8 + cb];
            #pragma unroll
            for (int rs = 0; rs < 2; rs++) {
                float sacc[4] = {0.f, 0.f, 0.f, 0.f};
                #pragma unroll
                for (int kb = 0; kb < 4; kb++)
                    mma16816(sacc, qh[rs][kb], bh[2 * kb], bh[2 * kb + 1]);
                rsum[rs][0] += __expf(sacc[0]) * s2.x + __expf(sacc[1]) * s2.y;
                rsum[rs][1] += __expf(sacc[2]) * s2.x + __expf(sacc[3]) * s2.y;
            }
        }
        __syncthreads();
    }

    #pragma unroll
    for (int rs = 0; rs < 2; rs++)
        #pragma unroll
        for (int hrow = 0; hrow < 2; hrow++) {
            float r = rsum[rs][hrow];
            r += __shfl_xor_sync(0xFFFFFFFFu, r, 1);
            r += __shfl_xor_sync(0xFFFFFFFFu, r, 2);
            if ((lane & 3) == 0)
                g_rinv[head * Ss + q0 + wid * 32 + rs * 16 + (lane >> 2) + hrow * 8] = 1.0f / r;
        }
}

// ---------- pass B: normalized attn + PV (hi-only, bit-identical QK to pass A) ----------
__global__ void __launch_bounds__(TPB, 1)
attn_kernel(const float* __restrict__ Q, const float* __restrict__ SENT,
            const int* __restrict__ MASK,
            float* __restrict__ OUT, float* __restrict__ ATTN)
{
    extern __shared__ char sm[];
    const uint32_t sb = smem_u32(sm);
    const int tid = threadIdx.x, lane = tid & 31, wid = tid >> 5;
    const int q0 = blockIdx.x * MT;
    const int head = blockIdx.y;
    const int b = head >> 4;
    const size_t head_off = (size_t)head * Ss;

    const unsigned char* scrK = g_scr + (size_t)head * SCR_HEAD;
    const unsigned char* scrV = g_scr + SCR_TENSOR + (size_t)head * SCR_HEAD;
    float* sentm = (float*)(sm + SM_SENT);
    const uint32_t bufb[2] = {sb + SM_BUF0, sb + SM_BUF1};

    {
        const float4* qg = (const float4*)(Q + (head_off + q0) * Dd);
        #pragma unroll
        for (int u = 0; u < 8; u++) {
            int idx = u * TPB + tid;
            int r = idx >> 3, c = idx & 7;
            float4 a = qg[r * 16 + c * 2], bq = qg[r * 16 + c * 2 + 1];
            uint4 H;
            H.x = cvt2h(a.x * INV_TEMP, a.y * INV_TEMP);
            H.y = cvt2h(a.z * INV_TEMP, a.w * INV_TEMP);
            H.z = cvt2h(bq.x * INV_TEMP, bq.y * INV_TEMP);
            H.w = cvt2h(bq.z * INV_TEMP, bq.w * INV_TEMP);
            *(uint4*)(sm + SM_QH + sw128((uint32_t)(r * 128 + c * 16))) = H;
        }
    }
    // tile 0: Khi|Vhi = 32KB
    {
        #pragma unroll
        for (int u = 0; u < 4; u++) {
            int i = (u * TPB + tid) * 16;
            cp16(bufb[0] + i, scrK + i);
            cp16(bufb[0] + 16384 + i, scrV + i);
        }
        CP_COMMIT();
    }
    __syncthreads();

    uint32_t qh[2][4][4];
    #pragma unroll
    for (int rs = 0; rs < 2; rs++) {
        uint32_t rowq = (uint32_t)(wid * 32 + rs * 16 + (lane & 15));
        #pragma unroll
        for (int kb = 0; kb < 4; kb++)
            ldsm4(qh[rs][kb], sb + SM_QH + sw128(rowq * 128 + ((uint32_t)(lane >> 4) + 2 * kb) * 16));
    }

    const int cb = 2 * (lane & 3);

    float inv[2][2];
    float* arow[2][2];
    #pragma unroll
    for (int rs = 0; rs < 2; rs++) {
        int row0 = wid * 32 + rs * 16 + (lane >> 2);
        inv[rs][0] = g_rinv[head * Ss + q0 + row0];
        inv[rs][1] = g_rinv[head * Ss + q0 + row0 + 8];
        arow[rs][0] = ATTN + (head_off + q0 + row0) * (size_t)Ss;
        arow[rs][1] = arow[rs][0] + 8 * (size_t)Ss;
    }

    float oacc[2][8][4];
    #pragma unroll
    for (int rs = 0; rs < 2; rs++)
        #pragma unroll
        for (int nb = 0; nb < 8; nb++)
            #pragma unroll
            for (int i = 0; i < 4; i++) oacc[rs][nb][i] = 0.f;

    for (int t = 0; t < NTL; t++) {
        const int j0 = t * KN;
        if (t + 1 < NTL) {
            const unsigned char* ks = scrK + (size_t)(t + 1) * SCR_TILE;
            const unsigned char* vs = scrV + (size_t)(t + 1) * SCR_TILE;
            #pragma unroll
            for (int u = 0; u < 4; u++) {
                int i = (u * TPB + tid) * 16;
                cp16(bufb[(t + 1) & 1] + i, ks + i);
                cp16(bufb[(t + 1) & 1] + 16384 + i, vs + i);
            }
            CP_COMMIT();
        }
        if (tid < KN) {
            int j = j0 + tid;
            sentm[(t & 1) * 128 + tid] = MASK[b * Ss + j] ? SENT[b * Ss + j] : 0.0f;
        }
        if (t + 1 < NTL) CP_WAIT1(); else CP_WAIT0();
        __syncthreads();

        const uint32_t kh_b = bufb[t & 1];
        const uint32_t vh_b = kh_b + 16384;
        const float* sm_s = sentm + (t & 1) * 128;

        #pragma unroll
        for (int kb = 0; kb < 8; kb++) {
            uint32_t pa[2][4];
            #pragma unroll
            for (int nbi = 0; nbi < 2; nbi++) {
                const int nb = 2 * kb + nbi;
                uint32_t bh[8];
                uint32_t rB = (uint32_t)(nb * 8 + (lane & 7)) * 128;
                uint32_t ch = (uint32_t)(lane >> 3) * 16;
                ldsm4(bh,     kh_b + sw128(rB + ch));
                ldsm4(bh + 4, kh_b + sw128(rB + ch + 64));
                float2 s2 = *(float2*)&sm_s[nb * 8 + cb];
                #pragma unroll
                for (int rs = 0; rs < 2; rs++) {
                    float sa[4] = {0.f, 0.f, 0.f, 0.f};
                    #pragma unroll
                    for (int kd = 0; kd < 4; kd++)
                        mma16816(sa, qh[rs][kd], bh[2 * kd], bh[2 * kd + 1]);
                    float p0 = __expf(sa[0]) * s2.x * inv[rs][0];
                    float p1 = __expf(sa[1]) * s2.y * inv[rs][0];
                    float p2 = __expf(sa[2]) * s2.x * inv[rs][1];
                    float p3 = __expf(sa[3]) * s2.y * inv[rs][1];
                    *(float2*)(arow[rs][0] + j0 + nb * 8 + cb) = make_float2(p0, p1);
                    *(float2*)(arow[rs][1] + j0 + nb * 8 + cb) = make_float2(p2, p3);
                    pa[rs][nbi * 2]     = cvt2h(p0, p1);
                    pa[rs][nbi * 2 + 1] = cvt2h(p2, p3);
                }
            }
            // PV (V-hi)
            uint32_t vh[16];
            uint32_t rV = (uint32_t)(kb * 16 + (lane & 15)) * 128;
            uint32_t chv = (uint32_t)(lane >> 4) * 16;
            #pragma unroll
            for (int qd = 0; qd < 4; qd++)
                ldsm4t(vh + 4 * qd, vh_b + sw128(rV + chv + qd * 32));
            #pragma unroll
            for (int rs = 0; rs < 2; rs++)
                #pragma unroll
                for (int nbd = 0; nbd < 8; nbd++)
                    mma16816(oacc[rs][nbd], pa[rs], vh[2 * nbd], vh[2 * nbd + 1]);
        }
        __syncthreads();
    }

    #pragma unroll
    for (int rs = 0; rs < 2; rs++) {
        int row0 = wid * 32 + rs * 16 + (lane >> 2);
        float2* o0 = (float2*)(OUT + (head_off + q0 + row0) * (size_t)Dd);
        float2* o1 = (float2*)(OUT + (head_off + q0 + row0 + 8) * (size_t)Dd);
        #pragma unroll
        for (int nbd = 0; nbd < 8; nbd++) {
            o0[nbd * 4 + (lane & 3)] = make_float2(oacc[rs][nbd][0], oacc[rs][nbd][1]);
            o1[nbd * 4 + (lane & 3)] = make_float2(oacc[rs][nbd][2], oacc[rs][nbd][3]);
        }
    }
}

extern "C" void kernel_launch(void* const* d_in, const int* in_sizes, int n_in,
                              void* d_out, int out_size)
{
    const float* q    = (const float*)d_in[0];
    const float* k    = (const float*)d_in[1];
    const float* v    = (const float*)d_in[2];
    const float* sent = (const float*)d_in[3];
    const int*   mask = (const int*)d_in[4];

    float* out  = (float*)d_out;                    // [B,H,S,D]
    float* attn = out + (size_t)Bb * Hh * Ss * Dd;  // [B,H,S,S]

    conv_kernel<<<4096, 256>>>(k, v);

    cudaFuncSetAttribute(passA_kernel, cudaFuncAttributeMaxDynamicSharedMemorySize, SMEM_A_BYTES);
    dim3 gridA(Ss / MT, Bb * Hh);
    passA_kernel<<<gridA, TPB, SMEM_A_BYTES>>>(q, sent, mask);

    cudaFuncSetAttribute(attn_kernel, cudaFuncAttributeMaxDynamicSharedMemorySize, SMEM_B_BYTES);
    dim3 gridB(Ss / MT, Bb * Hh);
    attn_kernel<<<gridB, TPB, SMEM_B_BYTES>>>(q, sent, mask, out, attn);
}